// round 12
// baseline (speedup 1.0000x reference)
#include <cuda_runtime.h>
#include <cuda_fp16.h>
#include <math_constants.h>
#include <cstdint>

// ---------------------------------------------------------------------------
// Problem constants
// ---------------------------------------------------------------------------
#define BB 4
#define TT 2048
#define CC 768
#define HH 768
#define MTOT (BB * TT)           // 8192
static const float QK_SCALE = 0.03608439182435161f;  // 1/sqrt(768)

// ---------------------------------------------------------------------------
// Scratch globals (operands fp16; scores fp32)
// ---------------------------------------------------------------------------
__device__ __half g_x [(size_t)MTOT * CC];
__device__ __half g_wt[(size_t)3 * CC * HH];    // W^T  [z][n][k]
__device__ __half g_q [(size_t)MTOT * HH];
__device__ __half g_k [(size_t)MTOT * HH];
__device__ __half g_v [(size_t)MTOT * HH];      // [t][h] per batch
__device__ float  g_s [(size_t)BB * TT * TT];   // raw scores (fp32)
__device__ __half g_p [(size_t)BB * TT * TT];   // softmax probs (fp16)

// ---------------------------------------------------------------------------
// GEMM config: CTA 128x128, 128 threads (4 warps 2x2), warp tile 64x64,
// fp16 m16n8k16 mma, K-chunk 64, 3-stage cp.async, ldmatrix.x4 fragments.
// At the mma.sync f32-acc throughput ceiling (~270 TF/s); this round packs
// the schedule: v-projection runs on a side stream concurrent with
// scores+softmax (fork/join events inside graph capture).
// ---------------------------------------------------------------------------
#define TM 128
#define TN 128
#define TK 64
#define STAGE_BYTES (2 * 128 * 128)       // A(16KB) + B(16KB)
#define NSTAGE 3
#define SMEM_BYTES (NSTAGE * STAGE_BYTES) // 98304

__device__ __forceinline__ uint32_t smem_u32(const void* p) {
    uint32_t a;
    asm("{ .reg .u64 t; cvta.to.shared.u64 t, %1; cvt.u32.u64 %0, t; }"
        : "=r"(a) : "l"(p));
    return a;
}

__device__ __forceinline__ void cp16(uint32_t dst, const void* src) {
    asm volatile("cp.async.cg.shared.global [%0], [%1], 16;"
                 :: "r"(dst), "l"(src) : "memory");
}

__device__ __forceinline__ void ldsm_x4(uint32_t r[4], uint32_t addr) {
    asm volatile("ldmatrix.sync.aligned.m8n8.x4.shared.b16 {%0,%1,%2,%3}, [%4];"
                 : "=r"(r[0]), "=r"(r[1]), "=r"(r[2]), "=r"(r[3]) : "r"(addr));
}

__device__ __forceinline__ void ldsm_x4_t(uint32_t r[4], uint32_t addr) {
    asm volatile("ldmatrix.sync.aligned.m8n8.x4.trans.shared.b16 {%0,%1,%2,%3}, [%4];"
                 : "=r"(r[0]), "=r"(r[1]), "=r"(r[2]), "=r"(r[3]) : "r"(addr));
}

__device__ __forceinline__ void mma_f16(float c[4], const uint32_t a[4],
                                        const uint32_t b0, const uint32_t b1) {
    asm volatile(
        "mma.sync.aligned.m16n8k16.row.col.f32.f16.f16.f32 "
        "{%0,%1,%2,%3}, {%4,%5,%6,%7}, {%8,%9}, {%0,%1,%2,%3};"
        : "+f"(c[0]), "+f"(c[1]), "+f"(c[2]), "+f"(c[3])
        : "r"(a[0]), "r"(a[1]), "r"(a[2]), "r"(a[3]), "r"(b0), "r"(b1));
}

// ---------------------------------------------------------------------------
// Generic 128x128 fp16 mma.sync GEMM tile.
// TRANSB=false: B is [n][k] fp16 (NT), 128B rows in smem.
// TRANSB=true : B is [k][n] fp16 (V layout), 256B rows in smem, trans-LDSM.
// ---------------------------------------------------------------------------
template <bool HALF_OUT, bool TRANSB>
__device__ __forceinline__ void gemm_tile(
    const __half* __restrict__ A, int lda,
    const __half* __restrict__ B, int ldb,
    void* __restrict__ Cv, int ldc,
    int row0, int col0, int K,
    const float* __restrict__ bias, float scale)
{
    extern __shared__ float smf[];
    const uint32_t sbase = smem_u32(smf);

    const int tid   = threadIdx.x;
    const int warp  = tid >> 5;
    const int lane  = tid & 31;
    const int wm    = (warp & 1) * 64;
    const int wn    = (warp >> 1) * 64;
    const int g     = lane >> 2;
    const int t     = lane & 3;

    const __half* Arow = A + (size_t)row0 * lda;
    const __half* Brow = TRANSB ? (B + col0) : (B + (size_t)col0 * ldb);
    const int NC = K / TK;

    float acc[4][8][4];
    #pragma unroll
    for (int mi = 0; mi < 4; mi++)
        #pragma unroll
        for (int ni = 0; ni < 8; ni++)
            #pragma unroll
            for (int j = 0; j < 4; j++) acc[mi][ni][j] = 0.0f;

    uint32_t stA[NSTAGE], stB[NSTAGE];
    #pragma unroll
    for (int s = 0; s < NSTAGE; s++) {
        stA[s] = sbase + (uint32_t)(s * STAGE_BYTES);
        stB[s] = stA[s] + (uint32_t)(128 * 128);
    }

    auto load_chunk = [&](uint32_t sA, uint32_t sB, int c) {
        const __half* Ag = Arow + c * TK;
        #pragma unroll
        for (int i = 0; i < 8; i++) {            // A: 128 rows x 8 granules
            int idx = tid + i * 128;
            int row = idx >> 3, gc = idx & 7;
            uint32_t off = (uint32_t)(row * 128 + ((gc * 16) ^ ((row & 7) * 16)));
            cp16(sA + off, Ag + (size_t)row * lda + gc * 8);
        }
        if (TRANSB) {
            const __half* Bg = Brow + (size_t)c * TK * ldb;
            #pragma unroll
            for (int i = 0; i < 8; i++) {        // B: 64 k-rows x 16 granules
                int idx = tid + i * 128;
                int row = idx >> 4, gc = idx & 15;
                uint32_t off = (uint32_t)(row * 256 + ((gc * 16) ^ ((row & 7) * 16)));
                cp16(sB + off, Bg + (size_t)row * ldb + gc * 8);
            }
        } else {
            const __half* Bg = Brow + c * TK;
            #pragma unroll
            for (int i = 0; i < 8; i++) {        // B: 128 n-rows x 8 granules
                int idx = tid + i * 128;
                int row = idx >> 3, gc = idx & 7;
                uint32_t off = (uint32_t)(row * 128 + ((gc * 16) ^ ((row & 7) * 16)));
                cp16(sB + off, Bg + (size_t)row * ldb + gc * 8);
            }
        }
    };

    #pragma unroll
    for (int s = 0; s < NSTAGE - 1; s++) {
        if (s < NC) load_chunk(stA[s], stB[s], s);
        asm volatile("cp.async.commit_group;" ::: "memory");
    }

    const uint32_t aRow = (uint32_t)(wm + (lane & 15)) * 128;
    const uint32_t bRow = (uint32_t)(wn + (lane & 15)) * 128;
    const uint32_t cHi  = (uint32_t)(lane >> 4) * 16;
    const uint32_t xr   = (uint32_t)(lane & 7) * 16;
    const uint32_t vRowB = (uint32_t)(lane & 15) * 256;
    uint32_t hx[4];
    #pragma unroll
    for (int p = 0; p < 4; p++)
        hx[p] = (uint32_t)((((wn >> 3) + 2 * p + (lane >> 4)) * 16) ^ ((lane & 7) * 16));

    #pragma unroll 1
    for (int c = 0; c < NC; c++) {
        asm volatile("cp.async.wait_group %0;" :: "n"(NSTAGE - 2) : "memory");
        __syncthreads();

        const int cn = c + NSTAGE - 1;
        if (cn < NC)
            load_chunk(stA[cn % NSTAGE], stB[cn % NSTAGE], cn);
        asm volatile("cp.async.commit_group;" ::: "memory");

        const int s = c % NSTAGE;
        const uint32_t aB = stA[s] + aRow;

        #pragma unroll
        for (int ks = 0; ks < 4; ks++) {
            uint32_t a[4][4], bf[4][4];
            const uint32_t koff = ((uint32_t)(2 * ks) * 16 + cHi) ^ xr;
            #pragma unroll
            for (int mi = 0; mi < 4; mi++)
                ldsm_x4(a[mi], aB + (uint32_t)mi * 2048 + koff);

            if (TRANSB) {
                const uint32_t bB = stB[s] + (uint32_t)ks * 4096 + vRowB;
                #pragma unroll
                for (int p = 0; p < 4; p++)
                    ldsm_x4_t(bf[p], bB + hx[p]);
                #pragma unroll
                for (int mi = 0; mi < 4; mi++)
                    #pragma unroll
                    for (int p = 0; p < 4; p++) {
                        mma_f16(acc[mi][2 * p],     a[mi], bf[p][0], bf[p][1]);
                        mma_f16(acc[mi][2 * p + 1], a[mi], bf[p][2], bf[p][3]);
                    }
            } else {
                const uint32_t bB = stB[s] + bRow;
                #pragma unroll
                for (int p = 0; p < 4; p++)
                    ldsm_x4(bf[p], bB + (uint32_t)p * 2048 + koff);
                #pragma unroll
                for (int mi = 0; mi < 4; mi++)
                    #pragma unroll
                    for (int p = 0; p < 4; p++) {
                        mma_f16(acc[mi][2 * p],     a[mi], bf[p][0], bf[p][2]);
                        mma_f16(acc[mi][2 * p + 1], a[mi], bf[p][1], bf[p][3]);
                    }
            }
        }
    }

    // Epilogue
    #pragma unroll
    for (int mi = 0; mi < 4; mi++) {
        const int r0 = row0 + wm + mi * 16 + g;
        #pragma unroll
        for (int ni = 0; ni < 8; ni++) {
            const int ccol = col0 + wn + ni * 8 + 2 * t;
            float v0 = acc[mi][ni][0] * scale;
            float v1 = acc[mi][ni][1] * scale;
            float v2 = acc[mi][ni][2] * scale;
            float v3 = acc[mi][ni][3] * scale;
            if (bias) {
                float b0 = bias[ccol], b1 = bias[ccol + 1];
                v0 += b0; v1 += b1; v2 += b0; v3 += b1;
            }
            if (HALF_OUT) {
                __half* C = (__half*)Cv;
                *(__half2*)(C + (size_t)r0 * ldc + ccol) = __floats2half2_rn(v0, v1);
                *(__half2*)(C + (size_t)(r0 + 8) * ldc + ccol) = __floats2half2_rn(v2, v3);
            } else {
                float* C = (float*)Cv;
                *(float2*)(C + (size_t)r0 * ldc + ccol) = make_float2(v0, v1);
                *(float2*)(C + (size_t)(r0 + 8) * ldc + ccol) = make_float2(v2, v3);
            }
        }
    }
}

// ---------------------------------------------------------------------------
// GEMM wrappers
// ---------------------------------------------------------------------------
__global__ __launch_bounds__(128, 2) void qk_mma(
    const float* __restrict__ bq, const float* __restrict__ bk)
{
    const int z = blockIdx.z;                 // 0 = q, 1 = k
    const float* bias = (z == 0) ? bq : bk;
    __half* out = (z == 0) ? g_q : g_k;
    const __half* B = g_wt + (size_t)z * CC * HH;
    gemm_tile<true, false>(g_x, CC, B, CC, out, HH,
                           blockIdx.y * TM, blockIdx.x * TN, CC, bias, 1.0f);
}

__global__ __launch_bounds__(128, 2) void v_mma(const float* __restrict__ bv)
{
    const __half* B = g_wt + (size_t)2 * CC * HH;
    gemm_tile<true, false>(g_x, CC, B, CC, g_v, HH,
                           blockIdx.y * TM, blockIdx.x * TN, CC, bv, 1.0f);
}

// Compact lower-triangular grid: 136 live tiles per batch, 544 CTAs total.
__global__ __launch_bounds__(128, 2) void scores_mma()
{
    const int b = blockIdx.x / 136;
    const int tidx = blockIdx.x % 136;
    int mi = (int)((sqrtf(8.0f * (float)tidx + 1.0f) - 1.0f) * 0.5f);
    while ((mi + 1) * (mi + 2) / 2 <= tidx) mi++;
    while (mi * (mi + 1) / 2 > tidx) mi--;
    const int nj = tidx - mi * (mi + 1) / 2;

    const __half* q = g_q + (size_t)b * TT * HH;
    const __half* k = g_k + (size_t)b * TT * HH;
    gemm_tile<false, false>(q, HH, k, HH, g_s + (size_t)b * TT * TT, TT,
                            mi * TM, nj * TN, HH, nullptr, QK_SCALE);
}

__global__ __launch_bounds__(128, 2) void pv_mma(float* __restrict__ out)
{
    const int nj = blockIdx.x, b = blockIdx.z;
    const int mi = (int)gridDim.y - 1 - (int)blockIdx.y;  // longest rows first
    const __half* P = g_p + (size_t)b * TT * TT;
    const __half* V = g_v + (size_t)b * TT * HH;          // [t][h]
    gemm_tile<false, true>(P, TT, V, HH, out + (size_t)b * TT * HH, HH,
                           mi * TM, nj * TN, (mi + 1) * TM, nullptr, 1.0f);
}

// ---------------------------------------------------------------------------
// Convert x to fp16 (8 elements/thread)
// ---------------------------------------------------------------------------
__global__ __launch_bounds__(256) void conv_x_kernel(const float* __restrict__ x)
{
    size_t i = (size_t)blockIdx.x * 256 + threadIdx.x;
    const float4* p = (const float4*)x + 2 * i;
    float4 v0 = p[0], v1 = p[1];
    __half2 h[4];
    h[0] = __floats2half2_rn(v0.x, v0.y);
    h[1] = __floats2half2_rn(v0.z, v0.w);
    h[2] = __floats2half2_rn(v1.x, v1.y);
    h[3] = __floats2half2_rn(v1.z, v1.w);
    ((uint4*)g_x)[i] = *(uint4*)h;
}

// ---------------------------------------------------------------------------
// W transpose (to fp16)
// ---------------------------------------------------------------------------
__global__ void transpose_w_kernel(const float* __restrict__ Wq,
                                   const float* __restrict__ Wk,
                                   const float* __restrict__ Wv)
{
    const int z = blockIdx.z;
    const float* src = (z == 0) ? Wq : (z == 1) ? Wk : Wv;
    __half* dst = g_wt + (size_t)z * CC * HH;
    __shared__ float t[32][33];
    const int c0 = blockIdx.x * 32, r0 = blockIdx.y * 32;
    const int tx = threadIdx.x, ty = threadIdx.y;
    #pragma unroll
    for (int i = 0; i < 4; i++)
        t[ty + 8 * i][tx] = src[(size_t)(r0 + ty + 8 * i) * HH + c0 + tx];
    __syncthreads();
    #pragma unroll
    for (int i = 0; i < 4; i++)
        dst[(size_t)(c0 + ty + 8 * i) * CC + r0 + tx] =
            __float2half_rn(t[tx][ty + 8 * i]);
}

// ---------------------------------------------------------------------------
// Causal row softmax: only the live tile range [0, Bnd) per row.
// ---------------------------------------------------------------------------
__global__ __launch_bounds__(256) void softmax_kernel()
{
    const int row = blockIdx.x;
    const int b = row / TT, i = row % TT;
    const float* S = g_s + (size_t)b * TT * TT + (size_t)i * TT;
    __half* P = g_p + (size_t)b * TT * TT + (size_t)i * TT;
    const int n = i + 1;
    const int Bnd = ((i >> 7) + 1) << 7;
    const int tid = threadIdx.x;
    const int base = tid * 8;
    const bool active = base < Bnd;

    float vals[8];
    #pragma unroll
    for (int jj = 0; jj < 8; jj++) vals[jj] = -CUDART_INF_F;
    if (active) {
        float4 u0 = ((const float4*)S)[tid * 2];
        float4 u1 = ((const float4*)S)[tid * 2 + 1];
        vals[0] = u0.x; vals[1] = u0.y; vals[2] = u0.z; vals[3] = u0.w;
        vals[4] = u1.x; vals[5] = u1.y; vals[6] = u1.z; vals[7] = u1.w;
        #pragma unroll
        for (int jj = 0; jj < 8; jj++)
            if (base + jj >= n) vals[jj] = -CUDART_INF_F;
    }

    __shared__ float red[256];
    float m = vals[0];
    #pragma unroll
    for (int jj = 1; jj < 8; jj++) m = fmaxf(m, vals[jj]);
    red[tid] = m;
    __syncthreads();
    #pragma unroll
    for (int s = 128; s > 0; s >>= 1) {
        if (tid < s) red[tid] = fmaxf(red[tid], red[tid + s]);
        __syncthreads();
    }
    m = red[0];
    __syncthreads();

    float e[8];
    float sum = 0.0f;
    #pragma unroll
    for (int jj = 0; jj < 8; jj++) {
        e[jj] = (vals[jj] == -CUDART_INF_F) ? 0.0f : __expf(vals[jj] - m);
        sum += e[jj];
    }
    red[tid] = sum;
    __syncthreads();
    #pragma unroll
    for (int s = 128; s > 0; s >>= 1) {
        if (tid < s) red[tid] += red[tid + s];
        __syncthreads();
    }
    const float inv = 1.0f / red[0];

    if (active) {
        __half2 h[4];
        #pragma unroll
        for (int jj = 0; jj < 4; jj++)
            h[jj] = __floats2half2_rn(e[2 * jj] * inv, e[2 * jj + 1] * inv);
        ((uint4*)P)[tid] = *(uint4*)h;
    }
}

// ---------------------------------------------------------------------------
// Launch: dual-stream fork/join. v_mma overlaps scores+softmax.
// ---------------------------------------------------------------------------
struct SideStream {
    cudaStream_t s;
    cudaEvent_t fork, join;
    SideStream() {
        cudaStreamCreateWithFlags(&s, cudaStreamNonBlocking);
        cudaEventCreateWithFlags(&fork, cudaEventDisableTiming);
        cudaEventCreateWithFlags(&join, cudaEventDisableTiming);
    }
};

extern "C" void kernel_launch(void* const* d_in, const int* in_sizes, int n_in,
                              void* d_out, int out_size)
{
    const float* x  = (const float*)d_in[0];
    const float* Wq = (const float*)d_in[1];
    const float* bq = (const float*)d_in[2];
    const float* Wk = (const float*)d_in[3];
    const float* bk = (const float*)d_in[4];
    const float* Wv = (const float*)d_in[5];
    const float* bv = (const float*)d_in[6];
    float* out = (float*)d_out;

    static SideStream side;   // host-side objects only; created once

    cudaFuncSetAttribute(qk_mma, cudaFuncAttributeMaxDynamicSharedMemorySize, SMEM_BYTES);
    cudaFuncSetAttribute(v_mma, cudaFuncAttributeMaxDynamicSharedMemorySize, SMEM_BYTES);
    cudaFuncSetAttribute(scores_mma, cudaFuncAttributeMaxDynamicSharedMemorySize, SMEM_BYTES);
    cudaFuncSetAttribute(pv_mma, cudaFuncAttributeMaxDynamicSharedMemorySize, SMEM_BYTES);

    conv_x_kernel<<<MTOT * CC / (256 * 8), 256>>>(x);
    transpose_w_kernel<<<dim3(HH / 32, CC / 32, 3), dim3(32, 8)>>>(Wq, Wk, Wv);
    qk_mma<<<dim3(HH / TN, MTOT / TM, 2), 128, SMEM_BYTES>>>(bq, bk);

    // Fork: v projection on the side stream (depends on conv_x + transpose_w,
    // both complete before this point on the main stream).
    cudaEventRecord(side.fork, 0);
    cudaStreamWaitEvent(side.s, side.fork, 0);
    v_mma<<<dim3(HH / TN, MTOT / TM, 1), 128, SMEM_BYTES, side.s>>>(bv);

    // Main stream: scores + softmax overlap with v_mma.
    scores_mma<<<dim3(136 * BB), 128, SMEM_BYTES>>>();
    softmax_kernel<<<dim3(BB * TT), 256>>>();

    // Join: pv needs both softmax (main) and v (side).
    cudaEventRecord(side.join, side.s);
    cudaStreamWaitEvent(0, side.join, 0);
    pv_mma<<<dim3(HH / TN, TT / TM, BB), 128, SMEM_BYTES>>>(out);
}

// round 13
// speedup vs baseline: 1.1131x; 1.1131x over previous
#include <cuda_runtime.h>
#include <cuda_fp16.h>
#include <math_constants.h>
#include <cstdint>

// ---------------------------------------------------------------------------
// Problem constants
// ---------------------------------------------------------------------------
#define BB 4
#define TT 2048
#define CC 768
#define HH 768
#define MTOT (BB * TT)           // 8192
static const float QK_SCALE = 0.03608439182435161f;  // 1/sqrt(768)

// ---------------------------------------------------------------------------
// Scratch globals
// ---------------------------------------------------------------------------
__device__ __half g_x   [(size_t)MTOT * CC];
__device__ __half g_wt  [(size_t)3 * CC * HH];   // W^T  [z][n][k]
__device__ __half g_q   [(size_t)MTOT * HH];
__device__ __half g_k   [(size_t)MTOT * HH];
__device__ __half g_v   [(size_t)MTOT * HH];     // [t][h] per batch
__device__ __half g_p   [(size_t)BB * TT * TT];  // exp(scores) fp16 (unnormalized)
__device__ float  g_psum[(size_t)MTOT * 32];     // per-(row, tile-half) partial sums
__device__ float  g_rinv[(size_t)MTOT];          // 1 / rowsum

// ---------------------------------------------------------------------------
// GEMM config: CTA 128x128, 128 threads (4 warps 2x2), warp tile 64x64,
// fp16 m16n8k16 mma, K-chunk 64, 3-stage cp.async, ldmatrix.x4 fragments.
// MODE 0: qkv   (half out + bias)
// MODE 1: scores (softmax epilogue: P=exp(s*scale) fp16 + per-row partial sums;
//                 no fp32 S ever materialized; softmax kernel deleted)
// MODE 2: pv    (float out, per-row 1/rowsum scaling, TRANSB V loads)
// ---------------------------------------------------------------------------
#define TM 128
#define TN 128
#define TK 64
#define STAGE_BYTES (2 * 128 * 128)       // A(16KB) + B(16KB)
#define NSTAGE 3
#define SMEM_BYTES (NSTAGE * STAGE_BYTES) // 98304 -> 2 CTAs/SM

__device__ __forceinline__ uint32_t smem_u32(const void* p) {
    uint32_t a;
    asm("{ .reg .u64 t; cvta.to.shared.u64 t, %1; cvt.u32.u64 %0, t; }"
        : "=r"(a) : "l"(p));
    return a;
}

__device__ __forceinline__ void cp16(uint32_t dst, const void* src) {
    asm volatile("cp.async.cg.shared.global [%0], [%1], 16;"
                 :: "r"(dst), "l"(src) : "memory");
}

__device__ __forceinline__ void ldsm_x4(uint32_t r[4], uint32_t addr) {
    asm volatile("ldmatrix.sync.aligned.m8n8.x4.shared.b16 {%0,%1,%2,%3}, [%4];"
                 : "=r"(r[0]), "=r"(r[1]), "=r"(r[2]), "=r"(r[3]) : "r"(addr));
}

__device__ __forceinline__ void ldsm_x4_t(uint32_t r[4], uint32_t addr) {
    asm volatile("ldmatrix.sync.aligned.m8n8.x4.trans.shared.b16 {%0,%1,%2,%3}, [%4];"
                 : "=r"(r[0]), "=r"(r[1]), "=r"(r[2]), "=r"(r[3]) : "r"(addr));
}

__device__ __forceinline__ void mma_f16(float c[4], const uint32_t a[4],
                                        const uint32_t b0, const uint32_t b1) {
    asm volatile(
        "mma.sync.aligned.m16n8k16.row.col.f32.f16.f16.f32 "
        "{%0,%1,%2,%3}, {%4,%5,%6,%7}, {%8,%9}, {%0,%1,%2,%3};"
        : "+f"(c[0]), "+f"(c[1]), "+f"(c[2]), "+f"(c[3])
        : "r"(a[0]), "r"(a[1]), "r"(a[2]), "r"(a[3]), "r"(b0), "r"(b1));
}

// ---------------------------------------------------------------------------
// Generic 128x128 fp16 mma.sync GEMM tile (MODE described above).
// aux: MODE 0 = bias (fp32, per col); MODE 1 = psum row base ptr
//      (g_psum + (b*TT+row0)*32); MODE 2 = rowscale (g_rinv + b*TT).
// pcol: MODE 1 partial-sum column base (nj*2).
// ---------------------------------------------------------------------------
template <int MODE>
__device__ __forceinline__ void gemm_tile(
    const __half* __restrict__ A, int lda,
    const __half* __restrict__ B, int ldb,
    void* __restrict__ Cv, int ldc,
    int row0, int col0, int K,
    const void* __restrict__ aux, float scale, int pcol)
{
    constexpr bool TRANSB = (MODE == 2);
    extern __shared__ float smf[];
    const uint32_t sbase = smem_u32(smf);

    const int tid   = threadIdx.x;
    const int warp  = tid >> 5;
    const int lane  = tid & 31;
    const int wm    = (warp & 1) * 64;
    const int wn    = (warp >> 1) * 64;
    const int g     = lane >> 2;
    const int t     = lane & 3;

    const __half* Arow = A + (size_t)row0 * lda;
    const __half* Brow = TRANSB ? (B + col0) : (B + (size_t)col0 * ldb);
    const int NC = K / TK;

    float acc[4][8][4];
    #pragma unroll
    for (int mi = 0; mi < 4; mi++)
        #pragma unroll
        for (int ni = 0; ni < 8; ni++)
            #pragma unroll
            for (int j = 0; j < 4; j++) acc[mi][ni][j] = 0.0f;

    uint32_t stA[NSTAGE], stB[NSTAGE];
    #pragma unroll
    for (int s = 0; s < NSTAGE; s++) {
        stA[s] = sbase + (uint32_t)(s * STAGE_BYTES);
        stB[s] = stA[s] + (uint32_t)(128 * 128);
    }

    auto load_chunk = [&](uint32_t sA, uint32_t sB, int c) {
        const __half* Ag = Arow + c * TK;
        #pragma unroll
        for (int i = 0; i < 8; i++) {            // A: 128 rows x 8 granules
            int idx = tid + i * 128;
            int row = idx >> 3, gc = idx & 7;
            uint32_t off = (uint32_t)(row * 128 + ((gc * 16) ^ ((row & 7) * 16)));
            cp16(sA + off, Ag + (size_t)row * lda + gc * 8);
        }
        if (TRANSB) {
            const __half* Bg = Brow + (size_t)c * TK * ldb;
            #pragma unroll
            for (int i = 0; i < 8; i++) {        // B: 64 k-rows x 16 granules
                int idx = tid + i * 128;
                int row = idx >> 4, gc = idx & 15;
                uint32_t off = (uint32_t)(row * 256 + ((gc * 16) ^ ((row & 7) * 16)));
                cp16(sB + off, Bg + (size_t)row * ldb + gc * 8);
            }
        } else {
            const __half* Bg = Brow + c * TK;
            #pragma unroll
            for (int i = 0; i < 8; i++) {        // B: 128 n-rows x 8 granules
                int idx = tid + i * 128;
                int row = idx >> 3, gc = idx & 7;
                uint32_t off = (uint32_t)(row * 128 + ((gc * 16) ^ ((row & 7) * 16)));
                cp16(sB + off, Bg + (size_t)row * ldb + gc * 8);
            }
        }
    };

    #pragma unroll
    for (int s = 0; s < NSTAGE - 1; s++) {
        if (s < NC) load_chunk(stA[s], stB[s], s);
        asm volatile("cp.async.commit_group;" ::: "memory");
    }

    const uint32_t aRow = (uint32_t)(wm + (lane & 15)) * 128;
    const uint32_t bRow = (uint32_t)(wn + (lane & 15)) * 128;
    const uint32_t cHi  = (uint32_t)(lane >> 4) * 16;
    const uint32_t xr   = (uint32_t)(lane & 7) * 16;
    const uint32_t vRowB = (uint32_t)(lane & 15) * 256;
    uint32_t hx[4];
    #pragma unroll
    for (int p = 0; p < 4; p++)
        hx[p] = (uint32_t)((((wn >> 3) + 2 * p + (lane >> 4)) * 16) ^ ((lane & 7) * 16));

    #pragma unroll 1
    for (int c = 0; c < NC; c++) {
        asm volatile("cp.async.wait_group %0;" :: "n"(NSTAGE - 2) : "memory");
        __syncthreads();

        const int cn = c + NSTAGE - 1;
        if (cn < NC)
            load_chunk(stA[cn % NSTAGE], stB[cn % NSTAGE], cn);
        asm volatile("cp.async.commit_group;" ::: "memory");

        const int s = c % NSTAGE;
        const uint32_t aB = stA[s] + aRow;

        #pragma unroll
        for (int ks = 0; ks < 4; ks++) {
            uint32_t a[4][4], bf[4][4];
            const uint32_t koff = ((uint32_t)(2 * ks) * 16 + cHi) ^ xr;
            #pragma unroll
            for (int mi = 0; mi < 4; mi++)
                ldsm_x4(a[mi], aB + (uint32_t)mi * 2048 + koff);

            if (TRANSB) {
                const uint32_t bB = stB[s] + (uint32_t)ks * 4096 + vRowB;
                #pragma unroll
                for (int p = 0; p < 4; p++)
                    ldsm_x4_t(bf[p], bB + hx[p]);
                #pragma unroll
                for (int mi = 0; mi < 4; mi++)
                    #pragma unroll
                    for (int p = 0; p < 4; p++) {
                        mma_f16(acc[mi][2 * p],     a[mi], bf[p][0], bf[p][1]);
                        mma_f16(acc[mi][2 * p + 1], a[mi], bf[p][2], bf[p][3]);
                    }
            } else {
                const uint32_t bB = stB[s] + bRow;
                #pragma unroll
                for (int p = 0; p < 4; p++)
                    ldsm_x4(bf[p], bB + (uint32_t)p * 2048 + koff);
                #pragma unroll
                for (int mi = 0; mi < 4; mi++)
                    #pragma unroll
                    for (int p = 0; p < 4; p++) {
                        mma_f16(acc[mi][2 * p],     a[mi], bf[p][0], bf[p][2]);
                        mma_f16(acc[mi][2 * p + 1], a[mi], bf[p][1], bf[p][3]);
                    }
            }
        }
    }

    // ------------------------------------------------------------- Epilogue
    if (MODE == 1) {
        // Softmax epilogue: P = exp(s*scale) fp16 (causal-masked),
        // per-row partial sums -> psum[row*32 + pcol + (wn>>6)].
        __half* C = (__half*)Cv;
        float* psum = (float*)aux;   // base = g_psum + (b*TT+row0)*32
        const int pc = pcol + (wn >> 6);
        #pragma unroll
        for (int mi = 0; mi < 4; mi++) {
            const int rA = row0 + wm + mi * 16 + g;   // batch-local rows
            const int rB = rA + 8;
            float sumA = 0.0f, sumB = 0.0f;
            #pragma unroll
            for (int ni = 0; ni < 8; ni++) {
                const int ccol = col0 + wn + ni * 8 + 2 * t;
                float e0 = (ccol     <= rA) ? __expf(acc[mi][ni][0] * scale) : 0.0f;
                float e1 = (ccol + 1 <= rA) ? __expf(acc[mi][ni][1] * scale) : 0.0f;
                float e2 = (ccol     <= rB) ? __expf(acc[mi][ni][2] * scale) : 0.0f;
                float e3 = (ccol + 1 <= rB) ? __expf(acc[mi][ni][3] * scale) : 0.0f;
                *(__half2*)(C + (size_t)rA * ldc + ccol) = __floats2half2_rn(e0, e1);
                *(__half2*)(C + (size_t)rB * ldc + ccol) = __floats2half2_rn(e2, e3);
                sumA += e0 + e1;
                sumB += e2 + e3;
            }
            sumA += __shfl_xor_sync(0xffffffffu, sumA, 1);
            sumA += __shfl_xor_sync(0xffffffffu, sumA, 2);
            sumB += __shfl_xor_sync(0xffffffffu, sumB, 1);
            sumB += __shfl_xor_sync(0xffffffffu, sumB, 2);
            if (t == 0) {
                psum[(size_t)(wm + mi * 16 + g) * 32 + pc] = sumA;
                psum[(size_t)(wm + mi * 16 + g + 8) * 32 + pc] = sumB;
            }
        }
        return;
    }

    #pragma unroll
    for (int mi = 0; mi < 4; mi++) {
        const int r0 = row0 + wm + mi * 16 + g;
        float rs0 = 1.0f, rs8 = 1.0f;
        if (MODE == 2) {
            const float* rowscale = (const float*)aux;
            rs0 = rowscale[r0];
            rs8 = rowscale[r0 + 8];
        }
        #pragma unroll
        for (int ni = 0; ni < 8; ni++) {
            const int ccol = col0 + wn + ni * 8 + 2 * t;
            float v0 = acc[mi][ni][0], v1 = acc[mi][ni][1];
            float v2 = acc[mi][ni][2], v3 = acc[mi][ni][3];
            if (MODE == 0) {
                const float* bias = (const float*)aux;
                float b0 = bias[ccol], b1 = bias[ccol + 1];
                v0 += b0; v1 += b1; v2 += b0; v3 += b1;
                __half* C = (__half*)Cv;
                *(__half2*)(C + (size_t)r0 * ldc + ccol) = __floats2half2_rn(v0, v1);
                *(__half2*)(C + (size_t)(r0 + 8) * ldc + ccol) = __floats2half2_rn(v2, v3);
            } else {  // MODE 2
                float* C = (float*)Cv;
                *(float2*)(C + (size_t)r0 * ldc + ccol) = make_float2(v0 * rs0, v1 * rs0);
                *(float2*)(C + (size_t)(r0 + 8) * ldc + ccol) = make_float2(v2 * rs8, v3 * rs8);
            }
        }
    }
}

// ---------------------------------------------------------------------------
// GEMM wrappers
// ---------------------------------------------------------------------------
__global__ __launch_bounds__(128, 2) void qkv_mma(
    const float* __restrict__ bq, const float* __restrict__ bk,
    const float* __restrict__ bv)
{
    const int z = blockIdx.z;
    const float* bias = (z == 0) ? bq : (z == 1) ? bk : bv;
    __half* out = (z == 0) ? g_q : (z == 1) ? g_k : g_v;
    const __half* B = g_wt + (size_t)z * CC * HH;
    gemm_tile<0>(g_x, CC, B, CC, out, HH,
                 blockIdx.y * TM, blockIdx.x * TN, CC, bias, 1.0f, 0);
}

// Compact lower-triangular grid: 136 live tiles per batch, 544 CTAs total.
__global__ __launch_bounds__(128, 2) void scores_mma()
{
    const int b = blockIdx.x / 136;
    const int tidx = blockIdx.x % 136;
    int mi = (int)((sqrtf(8.0f * (float)tidx + 1.0f) - 1.0f) * 0.5f);
    while ((mi + 1) * (mi + 2) / 2 <= tidx) mi++;
    while (mi * (mi + 1) / 2 > tidx) mi--;
    const int nj = tidx - mi * (mi + 1) / 2;

    const __half* q = g_q + (size_t)b * TT * HH;
    const __half* k = g_k + (size_t)b * TT * HH;
    float* psum = g_psum + (size_t)(b * TT + mi * TM) * 32;
    gemm_tile<1>(q, HH, k, HH, g_p + (size_t)b * TT * TT, TT,
                 mi * TM, nj * TN, HH, psum, QK_SCALE, nj * 2);
}

__global__ __launch_bounds__(128, 2) void pv_mma(float* __restrict__ out)
{
    const int nj = blockIdx.x, b = blockIdx.z;
    const int mi = (int)gridDim.y - 1 - (int)blockIdx.y;  // longest rows first
    const __half* P = g_p + (size_t)b * TT * TT;
    const __half* V = g_v + (size_t)b * TT * HH;          // [t][h]
    gemm_tile<2>(P, TT, V, HH, out + (size_t)b * TT * HH, HH,
                 mi * TM, nj * TN, (mi + 1) * TM, g_rinv + (size_t)b * TT,
                 1.0f, 0);
}

// ---------------------------------------------------------------------------
// Convert x to fp16 (8 elements/thread); first 256 blocks also zero g_psum.
// ---------------------------------------------------------------------------
__global__ __launch_bounds__(256) void conv_x_kernel(const float* __restrict__ x)
{
    size_t i = (size_t)blockIdx.x * 256 + threadIdx.x;
    if (blockIdx.x < 256) {
        ((float4*)g_psum)[i] = make_float4(0.f, 0.f, 0.f, 0.f);  // 256*256*4 = 256K floats
    }
    const float4* p = (const float4*)x + 2 * i;
    float4 v0 = p[0], v1 = p[1];
    __half2 h[4];
    h[0] = __floats2half2_rn(v0.x, v0.y);
    h[1] = __floats2half2_rn(v0.z, v0.w);
    h[2] = __floats2half2_rn(v1.x, v1.y);
    h[3] = __floats2half2_rn(v1.z, v1.w);
    ((uint4*)g_x)[i] = *(uint4*)h;
}

// ---------------------------------------------------------------------------
// W transpose (to fp16)
// ---------------------------------------------------------------------------
__global__ void transpose_w_kernel(const float* __restrict__ Wq,
                                   const float* __restrict__ Wk,
                                   const float* __restrict__ Wv)
{
    const int z = blockIdx.z;
    const float* src = (z == 0) ? Wq : (z == 1) ? Wk : Wv;
    __half* dst = g_wt + (size_t)z * CC * HH;
    __shared__ float t[32][33];
    const int c0 = blockIdx.x * 32, r0 = blockIdx.y * 32;
    const int tx = threadIdx.x, ty = threadIdx.y;
    #pragma unroll
    for (int i = 0; i < 4; i++)
        t[ty + 8 * i][tx] = src[(size_t)(r0 + ty + 8 * i) * HH + c0 + tx];
    __syncthreads();
    #pragma unroll
    for (int i = 0; i < 4; i++)
        dst[(size_t)(c0 + ty + 8 * i) * CC + r0 + tx] =
            __float2half_rn(t[tx][ty + 8 * i]);
}

// ---------------------------------------------------------------------------
// Row-sum reduce: rinv[row] = 1 / sum(psum[row][0..31])
// ---------------------------------------------------------------------------
__global__ __launch_bounds__(256) void rowsum_kernel()
{
    const int row = blockIdx.x * 256 + threadIdx.x;   // 0..8191
    const float4* p = (const float4*)(g_psum + (size_t)row * 32);
    float s = 0.0f;
    #pragma unroll
    for (int i = 0; i < 8; i++) {
        float4 v = p[i];
        s += (v.x + v.y) + (v.z + v.w);
    }
    g_rinv[row] = 1.0f / s;
}

// ---------------------------------------------------------------------------
// Launch (scores_mma is the 4th launch — ncu's profiled slot)
// ---------------------------------------------------------------------------
extern "C" void kernel_launch(void* const* d_in, const int* in_sizes, int n_in,
                              void* d_out, int out_size)
{
    const float* x  = (const float*)d_in[0];
    const float* Wq = (const float*)d_in[1];
    const float* bq = (const float*)d_in[2];
    const float* Wk = (const float*)d_in[3];
    const float* bk = (const float*)d_in[4];
    const float* Wv = (const float*)d_in[5];
    const float* bv = (const float*)d_in[6];
    float* out = (float*)d_out;

    cudaFuncSetAttribute(qkv_mma, cudaFuncAttributeMaxDynamicSharedMemorySize, SMEM_BYTES);
    cudaFuncSetAttribute(scores_mma, cudaFuncAttributeMaxDynamicSharedMemorySize, SMEM_BYTES);
    cudaFuncSetAttribute(pv_mma, cudaFuncAttributeMaxDynamicSharedMemorySize, SMEM_BYTES);

    conv_x_kernel<<<MTOT * CC / (256 * 8), 256>>>(x);
    transpose_w_kernel<<<dim3(HH / 32, CC / 32, 3), dim3(32, 8)>>>(Wq, Wk, Wv);
    qkv_mma<<<dim3(HH / TN, MTOT / TM, 3), 128, SMEM_BYTES>>>(bq, bk, bv);
    scores_mma<<<dim3(136 * BB), 128, SMEM_BYTES>>>();
    rowsum_kernel<<<MTOT / 256, 256>>>();
    pv_mma<<<dim3(HH / TN, TT / TM, BB), 128, SMEM_BYTES>>>(out);
}

// round 14
// speedup vs baseline: 1.1138x; 1.0006x over previous
#include <cuda_runtime.h>
#include <cuda_fp16.h>
#include <math_constants.h>
#include <cstdint>

// ---------------------------------------------------------------------------
// Problem constants
// ---------------------------------------------------------------------------
#define BB 4
#define TT 2048
#define CC 768
#define HH 768
#define MTOT (BB * TT)           // 8192
static const float QK_SCALE = 0.03608439182435161f;       // 1/sqrt(768)
static const float QK_SCALE_LOG2E = 0.05205971894527108f; // QK_SCALE * log2(e)

// ---------------------------------------------------------------------------
// Scratch globals
// ---------------------------------------------------------------------------
__device__ __half g_x   [(size_t)MTOT * CC];
__device__ __half g_wt  [(size_t)3 * CC * HH];   // W^T  [z][n][k]
__device__ __half g_q   [(size_t)MTOT * HH];
__device__ __half g_k   [(size_t)MTOT * HH];
__device__ __half g_v   [(size_t)MTOT * HH];     // [t][h] per batch
__device__ __half g_p   [(size_t)BB * TT * TT];  // exp(scores) fp16 (unnormalized)
__device__ float  g_psum[(size_t)MTOT * 32];     // per-(row, tile-half) partial sums
__device__ float  g_rinv[(size_t)MTOT];          // 1 / rowsum

// ---------------------------------------------------------------------------
// GEMM config: CTA 128x128, 128 threads (4 warps 2x2), warp tile 64x64,
// fp16 m16n8k16 mma, K-chunk 64, 3-stage cp.async, ldmatrix.x4 fragments.
// MODE 0: qkv    (half out + bias)
// MODE 1: scores (softmax epilogue: P=exp2(s*c) fp16 + per-row partial sums;
//                 MASK template: causal predicates only on diagonal tiles)
// MODE 2: pv     (float out, per-row 1/rowsum scaling, TRANSB V loads)
// ---------------------------------------------------------------------------
#define TM 128
#define TN 128
#define TK 64
#define STAGE_BYTES (2 * 128 * 128)       // A(16KB) + B(16KB)
#define NSTAGE 3
#define SMEM_BYTES (NSTAGE * STAGE_BYTES) // 98304 -> 2 CTAs/SM

__device__ __forceinline__ uint32_t smem_u32(const void* p) {
    uint32_t a;
    asm("{ .reg .u64 t; cvta.to.shared.u64 t, %1; cvt.u32.u64 %0, t; }"
        : "=r"(a) : "l"(p));
    return a;
}

__device__ __forceinline__ void cp16(uint32_t dst, const void* src) {
    asm volatile("cp.async.cg.shared.global [%0], [%1], 16;"
                 :: "r"(dst), "l"(src) : "memory");
}

__device__ __forceinline__ void ldsm_x4(uint32_t r[4], uint32_t addr) {
    asm volatile("ldmatrix.sync.aligned.m8n8.x4.shared.b16 {%0,%1,%2,%3}, [%4];"
                 : "=r"(r[0]), "=r"(r[1]), "=r"(r[2]), "=r"(r[3]) : "r"(addr));
}

__device__ __forceinline__ void ldsm_x4_t(uint32_t r[4], uint32_t addr) {
    asm volatile("ldmatrix.sync.aligned.m8n8.x4.trans.shared.b16 {%0,%1,%2,%3}, [%4];"
                 : "=r"(r[0]), "=r"(r[1]), "=r"(r[2]), "=r"(r[3]) : "r"(addr));
}

__device__ __forceinline__ void mma_f16(float c[4], const uint32_t a[4],
                                        const uint32_t b0, const uint32_t b1) {
    asm volatile(
        "mma.sync.aligned.m16n8k16.row.col.f32.f16.f16.f32 "
        "{%0,%1,%2,%3}, {%4,%5,%6,%7}, {%8,%9}, {%0,%1,%2,%3};"
        : "+f"(c[0]), "+f"(c[1]), "+f"(c[2]), "+f"(c[3])
        : "r"(a[0]), "r"(a[1]), "r"(a[2]), "r"(a[3]), "r"(b0), "r"(b1));
}

// ---------------------------------------------------------------------------
// Generic 128x128 fp16 mma.sync GEMM tile.
// aux: MODE 0 = bias; MODE 1 = psum row base; MODE 2 = rowscale.
// MASK: MODE 1 only — apply causal predicates (diagonal tiles).
// ---------------------------------------------------------------------------
template <int MODE, bool MASK>
__device__ __forceinline__ void gemm_tile(
    const __half* __restrict__ A, int lda,
    const __half* __restrict__ B, int ldb,
    void* __restrict__ Cv, int ldc,
    int row0, int col0, int K,
    const void* __restrict__ aux, float scale, int pcol)
{
    constexpr bool TRANSB = (MODE == 2);
    extern __shared__ float smf[];
    const uint32_t sbase = smem_u32(smf);

    const int tid   = threadIdx.x;
    const int warp  = tid >> 5;
    const int lane  = tid & 31;
    const int wm    = (warp & 1) * 64;
    const int wn    = (warp >> 1) * 64;
    const int g     = lane >> 2;
    const int t     = lane & 3;

    const __half* Arow = A + (size_t)row0 * lda;
    const __half* Brow = TRANSB ? (B + col0) : (B + (size_t)col0 * ldb);
    const int NC = K / TK;

    float acc[4][8][4];
    #pragma unroll
    for (int mi = 0; mi < 4; mi++)
        #pragma unroll
        for (int ni = 0; ni < 8; ni++)
            #pragma unroll
            for (int j = 0; j < 4; j++) acc[mi][ni][j] = 0.0f;

    uint32_t stA[NSTAGE], stB[NSTAGE];
    #pragma unroll
    for (int s = 0; s < NSTAGE; s++) {
        stA[s] = sbase + (uint32_t)(s * STAGE_BYTES);
        stB[s] = stA[s] + (uint32_t)(128 * 128);
    }

    auto load_chunk = [&](uint32_t sA, uint32_t sB, int c) {
        const __half* Ag = Arow + c * TK;
        #pragma unroll
        for (int i = 0; i < 8; i++) {            // A: 128 rows x 8 granules
            int idx = tid + i * 128;
            int row = idx >> 3, gc = idx & 7;
            uint32_t off = (uint32_t)(row * 128 + ((gc * 16) ^ ((row & 7) * 16)));
            cp16(sA + off, Ag + (size_t)row * lda + gc * 8);
        }
        if (TRANSB) {
            const __half* Bg = Brow + (size_t)c * TK * ldb;
            #pragma unroll
            for (int i = 0; i < 8; i++) {        // B: 64 k-rows x 16 granules
                int idx = tid + i * 128;
                int row = idx >> 4, gc = idx & 15;
                uint32_t off = (uint32_t)(row * 256 + ((gc * 16) ^ ((row & 7) * 16)));
                cp16(sB + off, Bg + (size_t)row * ldb + gc * 8);
            }
        } else {
            const __half* Bg = Brow + c * TK;
            #pragma unroll
            for (int i = 0; i < 8; i++) {        // B: 128 n-rows x 8 granules
                int idx = tid + i * 128;
                int row = idx >> 3, gc = idx & 7;
                uint32_t off = (uint32_t)(row * 128 + ((gc * 16) ^ ((row & 7) * 16)));
                cp16(sB + off, Bg + (size_t)row * ldb + gc * 8);
            }
        }
    };

    #pragma unroll
    for (int s = 0; s < NSTAGE - 1; s++) {
        if (s < NC) load_chunk(stA[s], stB[s], s);
        asm volatile("cp.async.commit_group;" ::: "memory");
    }

    const uint32_t aRow = (uint32_t)(wm + (lane & 15)) * 128;
    const uint32_t bRow = (uint32_t)(wn + (lane & 15)) * 128;
    const uint32_t cHi  = (uint32_t)(lane >> 4) * 16;
    const uint32_t xr   = (uint32_t)(lane & 7) * 16;
    const uint32_t vRowB = (uint32_t)(lane & 15) * 256;
    uint32_t hx[4];
    #pragma unroll
    for (int p = 0; p < 4; p++)
        hx[p] = (uint32_t)((((wn >> 3) + 2 * p + (lane >> 4)) * 16) ^ ((lane & 7) * 16));

    #pragma unroll 1
    for (int c = 0; c < NC; c++) {
        asm volatile("cp.async.wait_group %0;" :: "n"(NSTAGE - 2) : "memory");
        __syncthreads();

        const int cn = c + NSTAGE - 1;
        if (cn < NC)
            load_chunk(stA[cn % NSTAGE], stB[cn % NSTAGE], cn);
        asm volatile("cp.async.commit_group;" ::: "memory");

        const int s = c % NSTAGE;
        const uint32_t aB = stA[s] + aRow;

        #pragma unroll
        for (int ks = 0; ks < 4; ks++) {
            uint32_t a[4][4], bf[4][4];
            const uint32_t koff = ((uint32_t)(2 * ks) * 16 + cHi) ^ xr;
            #pragma unroll
            for (int mi = 0; mi < 4; mi++)
                ldsm_x4(a[mi], aB + (uint32_t)mi * 2048 + koff);

            if (TRANSB) {
                const uint32_t bB = stB[s] + (uint32_t)ks * 4096 + vRowB;
                #pragma unroll
                for (int p = 0; p < 4; p++)
                    ldsm_x4_t(bf[p], bB + hx[p]);
                #pragma unroll
                for (int mi = 0; mi < 4; mi++)
                    #pragma unroll
                    for (int p = 0; p < 4; p++) {
                        mma_f16(acc[mi][2 * p],     a[mi], bf[p][0], bf[p][1]);
                        mma_f16(acc[mi][2 * p + 1], a[mi], bf[p][2], bf[p][3]);
                    }
            } else {
                const uint32_t bB = stB[s] + bRow;
                #pragma unroll
                for (int p = 0; p < 4; p++)
                    ldsm_x4(bf[p], bB + (uint32_t)p * 2048 + koff);
                #pragma unroll
                for (int mi = 0; mi < 4; mi++)
                    #pragma unroll
                    for (int p = 0; p < 4; p++) {
                        mma_f16(acc[mi][2 * p],     a[mi], bf[p][0], bf[p][2]);
                        mma_f16(acc[mi][2 * p + 1], a[mi], bf[p][1], bf[p][3]);
                    }
            }
        }
    }

    // ------------------------------------------------------------- Epilogue
    if (MODE == 1) {
        // Softmax epilogue: P = exp2(s * scale_log2e) fp16, per-row partials.
        // MASK only on diagonal tiles; strictly-lower tiles skip predicates.
        __half* C = (__half*)Cv;
        float* psum = (float*)aux;
        const int pc = pcol + (wn >> 6);
        #pragma unroll
        for (int mi = 0; mi < 4; mi++) {
            const int rA = row0 + wm + mi * 16 + g;
            const int rB = rA + 8;
            float sumA = 0.0f, sumB = 0.0f;
            #pragma unroll
            for (int ni = 0; ni < 8; ni++) {
                const int ccol = col0 + wn + ni * 8 + 2 * t;
                float e0 = exp2f(acc[mi][ni][0] * scale);
                float e1 = exp2f(acc[mi][ni][1] * scale);
                float e2 = exp2f(acc[mi][ni][2] * scale);
                float e3 = exp2f(acc[mi][ni][3] * scale);
                if (MASK) {
                    if (ccol     > rA) e0 = 0.0f;
                    if (ccol + 1 > rA) e1 = 0.0f;
                    if (ccol     > rB) e2 = 0.0f;
                    if (ccol + 1 > rB) e3 = 0.0f;
                }
                *(__half2*)(C + (size_t)rA * ldc + ccol) = __floats2half2_rn(e0, e1);
                *(__half2*)(C + (size_t)rB * ldc + ccol) = __floats2half2_rn(e2, e3);
                sumA += e0 + e1;
                sumB += e2 + e3;
            }
            sumA += __shfl_xor_sync(0xffffffffu, sumA, 1);
            sumA += __shfl_xor_sync(0xffffffffu, sumA, 2);
            sumB += __shfl_xor_sync(0xffffffffu, sumB, 1);
            sumB += __shfl_xor_sync(0xffffffffu, sumB, 2);
            if (t == 0) {
                psum[(size_t)(wm + mi * 16 + g) * 32 + pc] = sumA;
                psum[(size_t)(wm + mi * 16 + g + 8) * 32 + pc] = sumB;
            }
        }
        return;
    }

    #pragma unroll
    for (int mi = 0; mi < 4; mi++) {
        const int r0 = row0 + wm + mi * 16 + g;
        float rs0 = 1.0f, rs8 = 1.0f;
        if (MODE == 2) {
            const float* rowscale = (const float*)aux;
            rs0 = rowscale[r0];
            rs8 = rowscale[r0 + 8];
        }
        #pragma unroll
        for (int ni = 0; ni < 8; ni++) {
            const int ccol = col0 + wn + ni * 8 + 2 * t;
            float v0 = acc[mi][ni][0], v1 = acc[mi][ni][1];
            float v2 = acc[mi][ni][2], v3 = acc[mi][ni][3];
            if (MODE == 0) {
                const float* bias = (const float*)aux;
                float b0 = bias[ccol], b1 = bias[ccol + 1];
                v0 += b0; v1 += b1; v2 += b0; v3 += b1;
                __half* C = (__half*)Cv;
                *(__half2*)(C + (size_t)r0 * ldc + ccol) = __floats2half2_rn(v0, v1);
                *(__half2*)(C + (size_t)(r0 + 8) * ldc + ccol) = __floats2half2_rn(v2, v3);
            } else {  // MODE 2
                float* C = (float*)Cv;
                *(float2*)(C + (size_t)r0 * ldc + ccol) = make_float2(v0 * rs0, v1 * rs0);
                *(float2*)(C + (size_t)(r0 + 8) * ldc + ccol) = make_float2(v2 * rs8, v3 * rs8);
            }
        }
    }
}

// ---------------------------------------------------------------------------
// GEMM wrappers
// ---------------------------------------------------------------------------
__global__ __launch_bounds__(128, 2) void qkv_mma(
    const float* __restrict__ bq, const float* __restrict__ bk,
    const float* __restrict__ bv)
{
    const int z = blockIdx.z;
    const float* bias = (z == 0) ? bq : (z == 1) ? bk : bv;
    __half* out = (z == 0) ? g_q : (z == 1) ? g_k : g_v;
    const __half* B = g_wt + (size_t)z * CC * HH;
    gemm_tile<0, false>(g_x, CC, B, CC, out, HH,
                        blockIdx.y * TM, blockIdx.x * TN, CC, bias, 1.0f, 0);
}

// Compact lower-triangular grid: 136 live tiles per batch, 544 CTAs total.
__global__ __launch_bounds__(128, 2) void scores_mma()
{
    const int b = blockIdx.x / 136;
    const int tidx = blockIdx.x % 136;
    int mi = (int)((sqrtf(8.0f * (float)tidx + 1.0f) - 1.0f) * 0.5f);
    while ((mi + 1) * (mi + 2) / 2 <= tidx) mi++;
    while (mi * (mi + 1) / 2 > tidx) mi--;
    const int nj = tidx - mi * (mi + 1) / 2;

    const __half* q = g_q + (size_t)b * TT * HH;
    const __half* k = g_k + (size_t)b * TT * HH;
    float* psum = g_psum + (size_t)(b * TT + mi * TM) * 32;
    __half* P = g_p + (size_t)b * TT * TT;
    if (nj == mi)   // diagonal tile: needs causal mask
        gemm_tile<1, true>(q, HH, k, HH, P, TT,
                           mi * TM, nj * TN, HH, psum, QK_SCALE_LOG2E, nj * 2);
    else            // strictly lower: mask-free epilogue
        gemm_tile<1, false>(q, HH, k, HH, P, TT,
                            mi * TM, nj * TN, HH, psum, QK_SCALE_LOG2E, nj * 2);
}

__global__ __launch_bounds__(128, 2) void pv_mma(float* __restrict__ out)
{
    const int nj = blockIdx.x, b = blockIdx.z;
    const int mi = (int)gridDim.y - 1 - (int)blockIdx.y;  // longest rows first
    const __half* P = g_p + (size_t)b * TT * TT;
    const __half* V = g_v + (size_t)b * TT * HH;          // [t][h]
    gemm_tile<2, false>(P, TT, V, HH, out + (size_t)b * TT * HH, HH,
                        mi * TM, nj * TN, (mi + 1) * TM, g_rinv + (size_t)b * TT,
                        1.0f, 0);
}

// ---------------------------------------------------------------------------
// Convert x to fp16 (8 elements/thread); first 256 blocks also zero g_psum.
// ---------------------------------------------------------------------------
__global__ __launch_bounds__(256) void conv_x_kernel(const float* __restrict__ x)
{
    size_t i = (size_t)blockIdx.x * 256 + threadIdx.x;
    if (blockIdx.x < 256) {
        ((float4*)g_psum)[i] = make_float4(0.f, 0.f, 0.f, 0.f);
    }
    const float4* p = (const float4*)x + 2 * i;
    float4 v0 = p[0], v1 = p[1];
    __half2 h[4];
    h[0] = __floats2half2_rn(v0.x, v0.y);
    h[1] = __floats2half2_rn(v0.z, v0.w);
    h[2] = __floats2half2_rn(v1.x, v1.y);
    h[3] = __floats2half2_rn(v1.z, v1.w);
    ((uint4*)g_x)[i] = *(uint4*)h;
}

// ---------------------------------------------------------------------------
// W transpose (to fp16)
// ---------------------------------------------------------------------------
__global__ void transpose_w_kernel(const float* __restrict__ Wq,
                                   const float* __restrict__ Wk,
                                   const float* __restrict__ Wv)
{
    const int z = blockIdx.z;
    const float* src = (z == 0) ? Wq : (z == 1) ? Wk : Wv;
    __half* dst = g_wt + (size_t)z * CC * HH;
    __shared__ float t[32][33];
    const int c0 = blockIdx.x * 32, r0 = blockIdx.y * 32;
    const int tx = threadIdx.x, ty = threadIdx.y;
    #pragma unroll
    for (int i = 0; i < 4; i++)
        t[ty + 8 * i][tx] = src[(size_t)(r0 + ty + 8 * i) * HH + c0 + tx];
    __syncthreads();
    #pragma unroll
    for (int i = 0; i < 4; i++)
        dst[(size_t)(c0 + ty + 8 * i) * CC + r0 + tx] =
            __float2half_rn(t[tx][ty + 8 * i]);
}

// ---------------------------------------------------------------------------
// Row-sum reduce: rinv[row] = 1 / sum(psum[row][0..31])
// ---------------------------------------------------------------------------
__global__ __launch_bounds__(256) void rowsum_kernel()
{
    const int row = blockIdx.x * 256 + threadIdx.x;
    const float4* p = (const float4*)(g_psum + (size_t)row * 32);
    float s = 0.0f;
    #pragma unroll
    for (int i = 0; i < 8; i++) {
        float4 v = p[i];
        s += (v.x + v.y) + (v.z + v.w);
    }
    g_rinv[row] = 1.0f / s;
}

// ---------------------------------------------------------------------------
// Launch (scores_mma is the 4th launch — ncu's profiled slot)
// ---------------------------------------------------------------------------
extern "C" void kernel_launch(void* const* d_in, const int* in_sizes, int n_in,
                              void* d_out, int out_size)
{
    const float* x  = (const float*)d_in[0];
    const float* Wq = (const float*)d_in[1];
    const float* bq = (const float*)d_in[2];
    const float* Wk = (const float*)d_in[3];
    const float* bk = (const float*)d_in[4];
    const float* Wv = (const float*)d_in[5];
    const float* bv = (const float*)d_in[6];
    float* out = (float*)d_out;

    cudaFuncSetAttribute(qkv_mma, cudaFuncAttributeMaxDynamicSharedMemorySize, SMEM_BYTES);
    cudaFuncSetAttribute(scores_mma, cudaFuncAttributeMaxDynamicSharedMemorySize, SMEM_BYTES);
    cudaFuncSetAttribute(pv_mma, cudaFuncAttributeMaxDynamicSharedMemorySize, SMEM_BYTES);

    conv_x_kernel<<<MTOT * CC / (256 * 8), 256>>>(x);
    transpose_w_kernel<<<dim3(HH / 32, CC / 32, 3), dim3(32, 8)>>>(Wq, Wk, Wv);
    qkv_mma<<<dim3(HH / TN, MTOT / TM, 3), 128, SMEM_BYTES>>>(bq, bk, bv);
    scores_mma<<<dim3(136 * BB), 128, SMEM_BYTES>>>();
    rowsum_kernel<<<MTOT / 256, 256>>>();
    pv_mma<<<dim3(HH / TN, TT / TM, BB), 128, SMEM_BYTES>>>(out);
}

// round 15
// speedup vs baseline: 1.1359x; 1.0198x over previous
#include <cuda_runtime.h>
#include <cuda_fp16.h>
#include <math_constants.h>
#include <cstdint>

// ---------------------------------------------------------------------------
// Problem constants
// ---------------------------------------------------------------------------
#define BB 4
#define TT 2048
#define CC 768
#define HH 768
#define MTOT (BB * TT)           // 8192
static const float QK_SCALE_LOG2E = 0.05205971894527108f; // (1/sqrt(768))*log2(e)

// ---------------------------------------------------------------------------
// Scratch globals
// ---------------------------------------------------------------------------
__device__ __half g_x   [(size_t)MTOT * CC];
__device__ __half g_wt  [(size_t)3 * CC * HH];   // W^T  [z][n][k]
__device__ __half g_q   [(size_t)MTOT * HH];
__device__ __half g_k   [(size_t)MTOT * HH];
__device__ __half g_v   [(size_t)MTOT * HH];     // [t][h] per batch
__device__ __half g_p   [(size_t)BB * TT * TT];  // exp(scores) fp16 (unnormalized)
__device__ float  g_psum[(size_t)MTOT * 32];     // per-(row, tile-half) partial sums

// ---------------------------------------------------------------------------
// GEMM config: CTA 128x128, 128 threads (4 warps 2x2), warp tile 64x64,
// fp16 m16n8k16 mma, K-chunk 64, 3-stage cp.async, ldmatrix.x4 fragments.
// MODE 0: qkv    (half out + bias)
// MODE 1: scores (softmax epilogue; MASK only on diagonal tiles)
// MODE 2: pv     (float out; rowsum reduced from psum IN the epilogue)
// ---------------------------------------------------------------------------
#define TM 128
#define TN 128
#define TK 64
#define STAGE_BYTES (2 * 128 * 128)       // A(16KB) + B(16KB)
#define NSTAGE 3
#define SMEM_BYTES (NSTAGE * STAGE_BYTES) // 98304 -> 2 CTAs/SM

__device__ __forceinline__ uint32_t smem_u32(const void* p) {
    uint32_t a;
    asm("{ .reg .u64 t; cvta.to.shared.u64 t, %1; cvt.u32.u64 %0, t; }"
        : "=r"(a) : "l"(p));
    return a;
}

__device__ __forceinline__ void cp16(uint32_t dst, const void* src) {
    asm volatile("cp.async.cg.shared.global [%0], [%1], 16;"
                 :: "r"(dst), "l"(src) : "memory");
}

__device__ __forceinline__ void ldsm_x4(uint32_t r[4], uint32_t addr) {
    asm volatile("ldmatrix.sync.aligned.m8n8.x4.shared.b16 {%0,%1,%2,%3}, [%4];"
                 : "=r"(r[0]), "=r"(r[1]), "=r"(r[2]), "=r"(r[3]) : "r"(addr));
}

__device__ __forceinline__ void ldsm_x4_t(uint32_t r[4], uint32_t addr) {
    asm volatile("ldmatrix.sync.aligned.m8n8.x4.trans.shared.b16 {%0,%1,%2,%3}, [%4];"
                 : "=r"(r[0]), "=r"(r[1]), "=r"(r[2]), "=r"(r[3]) : "r"(addr));
}

__device__ __forceinline__ void mma_f16(float c[4], const uint32_t a[4],
                                        const uint32_t b0, const uint32_t b1) {
    asm volatile(
        "mma.sync.aligned.m16n8k16.row.col.f32.f16.f16.f32 "
        "{%0,%1,%2,%3}, {%4,%5,%6,%7}, {%8,%9}, {%0,%1,%2,%3};"
        : "+f"(c[0]), "+f"(c[1]), "+f"(c[2]), "+f"(c[3])
        : "r"(a[0]), "r"(a[1]), "r"(a[2]), "r"(a[3]), "r"(b0), "r"(b1));
}

// ---------------------------------------------------------------------------
// Generic 128x128 fp16 mma.sync GEMM tile.
// aux: MODE 0 = bias; MODE 1 = psum row base (g_psum + (b*TT+row0)*32);
//      MODE 2 = psum batch-local base (g_psum + b*TT*32).
// ---------------------------------------------------------------------------
template <int MODE, bool MASK>
__device__ __forceinline__ void gemm_tile(
    const __half* __restrict__ A, int lda,
    const __half* __restrict__ B, int ldb,
    void* __restrict__ Cv, int ldc,
    int row0, int col0, int K,
    const void* __restrict__ aux, float scale, int pcol)
{
    constexpr bool TRANSB = (MODE == 2);
    extern __shared__ float smf[];
    const uint32_t sbase = smem_u32(smf);

    const int tid   = threadIdx.x;
    const int warp  = tid >> 5;
    const int lane  = tid & 31;
    const int wm    = (warp & 1) * 64;
    const int wn    = (warp >> 1) * 64;
    const int g     = lane >> 2;
    const int t     = lane & 3;

    const __half* Arow = A + (size_t)row0 * lda;
    const __half* Brow = TRANSB ? (B + col0) : (B + (size_t)col0 * ldb);
    const int NC = K / TK;

    float acc[4][8][4];
    #pragma unroll
    for (int mi = 0; mi < 4; mi++)
        #pragma unroll
        for (int ni = 0; ni < 8; ni++)
            #pragma unroll
            for (int j = 0; j < 4; j++) acc[mi][ni][j] = 0.0f;

    uint32_t stA[NSTAGE], stB[NSTAGE];
    #pragma unroll
    for (int s = 0; s < NSTAGE; s++) {
        stA[s] = sbase + (uint32_t)(s * STAGE_BYTES);
        stB[s] = stA[s] + (uint32_t)(128 * 128);
    }

    auto load_chunk = [&](uint32_t sA, uint32_t sB, int c) {
        const __half* Ag = Arow + c * TK;
        #pragma unroll
        for (int i = 0; i < 8; i++) {            // A: 128 rows x 8 granules
            int idx = tid + i * 128;
            int row = idx >> 3, gc = idx & 7;
            uint32_t off = (uint32_t)(row * 128 + ((gc * 16) ^ ((row & 7) * 16)));
            cp16(sA + off, Ag + (size_t)row * lda + gc * 8);
        }
        if (TRANSB) {
            const __half* Bg = Brow + (size_t)c * TK * ldb;
            #pragma unroll
            for (int i = 0; i < 8; i++) {        // B: 64 k-rows x 16 granules
                int idx = tid + i * 128;
                int row = idx >> 4, gc = idx & 15;
                uint32_t off = (uint32_t)(row * 256 + ((gc * 16) ^ ((row & 7) * 16)));
                cp16(sB + off, Bg + (size_t)row * ldb + gc * 8);
            }
        } else {
            const __half* Bg = Brow + c * TK;
            #pragma unroll
            for (int i = 0; i < 8; i++) {        // B: 128 n-rows x 8 granules
                int idx = tid + i * 128;
                int row = idx >> 3, gc = idx & 7;
                uint32_t off = (uint32_t)(row * 128 + ((gc * 16) ^ ((row & 7) * 16)));
                cp16(sB + off, Bg + (size_t)row * ldb + gc * 8);
            }
        }
    };

    #pragma unroll
    for (int s = 0; s < NSTAGE - 1; s++) {
        if (s < NC) load_chunk(stA[s], stB[s], s);
        asm volatile("cp.async.commit_group;" ::: "memory");
    }

    const uint32_t aRow = (uint32_t)(wm + (lane & 15)) * 128;
    const uint32_t bRow = (uint32_t)(wn + (lane & 15)) * 128;
    const uint32_t cHi  = (uint32_t)(lane >> 4) * 16;
    const uint32_t xr   = (uint32_t)(lane & 7) * 16;
    const uint32_t vRowB = (uint32_t)(lane & 15) * 256;
    uint32_t hx[4];
    #pragma unroll
    for (int p = 0; p < 4; p++)
        hx[p] = (uint32_t)((((wn >> 3) + 2 * p + (lane >> 4)) * 16) ^ ((lane & 7) * 16));

    #pragma unroll 1
    for (int c = 0; c < NC; c++) {
        asm volatile("cp.async.wait_group %0;" :: "n"(NSTAGE - 2) : "memory");
        __syncthreads();

        const int cn = c + NSTAGE - 1;
        if (cn < NC)
            load_chunk(stA[cn % NSTAGE], stB[cn % NSTAGE], cn);
        asm volatile("cp.async.commit_group;" ::: "memory");

        const int s = c % NSTAGE;
        const uint32_t aB = stA[s] + aRow;

        #pragma unroll
        for (int ks = 0; ks < 4; ks++) {
            uint32_t a[4][4], bf[4][4];
            const uint32_t koff = ((uint32_t)(2 * ks) * 16 + cHi) ^ xr;
            #pragma unroll
            for (int mi = 0; mi < 4; mi++)
                ldsm_x4(a[mi], aB + (uint32_t)mi * 2048 + koff);

            if (TRANSB) {
                const uint32_t bB = stB[s] + (uint32_t)ks * 4096 + vRowB;
                #pragma unroll
                for (int p = 0; p < 4; p++)
                    ldsm_x4_t(bf[p], bB + hx[p]);
                #pragma unroll
                for (int mi = 0; mi < 4; mi++)
                    #pragma unroll
                    for (int p = 0; p < 4; p++) {
                        mma_f16(acc[mi][2 * p],     a[mi], bf[p][0], bf[p][1]);
                        mma_f16(acc[mi][2 * p + 1], a[mi], bf[p][2], bf[p][3]);
                    }
            } else {
                const uint32_t bB = stB[s] + bRow;
                #pragma unroll
                for (int p = 0; p < 4; p++)
                    ldsm_x4(bf[p], bB + (uint32_t)p * 2048 + koff);
                #pragma unroll
                for (int mi = 0; mi < 4; mi++)
                    #pragma unroll
                    for (int p = 0; p < 4; p++) {
                        mma_f16(acc[mi][2 * p],     a[mi], bf[p][0], bf[p][2]);
                        mma_f16(acc[mi][2 * p + 1], a[mi], bf[p][1], bf[p][3]);
                    }
            }
        }
    }

    // ------------------------------------------------------------- Epilogue
    if (MODE == 1) {
        // P = exp2(s * scale_log2e) fp16, per-row partial sums.
        __half* C = (__half*)Cv;
        float* psum = (float*)aux;
        const int pc = pcol + (wn >> 6);
        #pragma unroll
        for (int mi = 0; mi < 4; mi++) {
            const int rA = row0 + wm + mi * 16 + g;
            const int rB = rA + 8;
            float sumA = 0.0f, sumB = 0.0f;
            #pragma unroll
            for (int ni = 0; ni < 8; ni++) {
                const int ccol = col0 + wn + ni * 8 + 2 * t;
                float e0 = exp2f(acc[mi][ni][0] * scale);
                float e1 = exp2f(acc[mi][ni][1] * scale);
                float e2 = exp2f(acc[mi][ni][2] * scale);
                float e3 = exp2f(acc[mi][ni][3] * scale);
                if (MASK) {
                    if (ccol     > rA) e0 = 0.0f;
                    if (ccol + 1 > rA) e1 = 0.0f;
                    if (ccol     > rB) e2 = 0.0f;
                    if (ccol + 1 > rB) e3 = 0.0f;
                }
                *(__half2*)(C + (size_t)rA * ldc + ccol) = __floats2half2_rn(e0, e1);
                *(__half2*)(C + (size_t)rB * ldc + ccol) = __floats2half2_rn(e2, e3);
                sumA += e0 + e1;
                sumB += e2 + e3;
            }
            sumA += __shfl_xor_sync(0xffffffffu, sumA, 1);
            sumA += __shfl_xor_sync(0xffffffffu, sumA, 2);
            sumB += __shfl_xor_sync(0xffffffffu, sumB, 1);
            sumB += __shfl_xor_sync(0xffffffffu, sumB, 2);
            if (t == 0) {
                psum[(size_t)(wm + mi * 16 + g) * 32 + pc] = sumA;
                psum[(size_t)(wm + mi * 16 + g + 8) * 32 + pc] = sumB;
            }
        }
        return;
    }

    #pragma unroll
    for (int mi = 0; mi < 4; mi++) {
        const int r0 = row0 + wm + mi * 16 + g;
        float rs0 = 1.0f, rs8 = 1.0f;
        if (MODE == 2) {
            // Rowsum reduced here from psum (batch-local base in aux):
            // thread t sums 8 of the 32 partials, quad-shfl combines.
            const float* psum = (const float*)aux;
            const float4* p0 = (const float4*)(psum + (size_t)r0 * 32) + t * 2;
            const float4* p8 = (const float4*)(psum + (size_t)(r0 + 8) * 32) + t * 2;
            float4 a0 = p0[0], a1 = p0[1];
            float4 b0 = p8[0], b1 = p8[1];
            float s0 = (a0.x + a0.y) + (a0.z + a0.w) + (a1.x + a1.y) + (a1.z + a1.w);
            float s8 = (b0.x + b0.y) + (b0.z + b0.w) + (b1.x + b1.y) + (b1.z + b1.w);
            s0 += __shfl_xor_sync(0xffffffffu, s0, 1);
            s0 += __shfl_xor_sync(0xffffffffu, s0, 2);
            s8 += __shfl_xor_sync(0xffffffffu, s8, 1);
            s8 += __shfl_xor_sync(0xffffffffu, s8, 2);
            rs0 = 1.0f / s0;
            rs8 = 1.0f / s8;
        }
        #pragma unroll
        for (int ni = 0; ni < 8; ni++) {
            const int ccol = col0 + wn + ni * 8 + 2 * t;
            float v0 = acc[mi][ni][0], v1 = acc[mi][ni][1];
            float v2 = acc[mi][ni][2], v3 = acc[mi][ni][3];
            if (MODE == 0) {
                const float* bias = (const float*)aux;
                float b0 = bias[ccol], b1 = bias[ccol + 1];
                v0 += b0; v1 += b1; v2 += b0; v3 += b1;
                __half* C = (__half*)Cv;
                *(__half2*)(C + (size_t)r0 * ldc + ccol) = __floats2half2_rn(v0, v1);
                *(__half2*)(C + (size_t)(r0 + 8) * ldc + ccol) = __floats2half2_rn(v2, v3);
            } else {  // MODE 2
                float* C = (float*)Cv;
                *(float2*)(C + (size_t)r0 * ldc + ccol) = make_float2(v0 * rs0, v1 * rs0);
                *(float2*)(C + (size_t)(r0 + 8) * ldc + ccol) = make_float2(v2 * rs8, v3 * rs8);
            }
        }
    }
}

// ---------------------------------------------------------------------------
// GEMM wrappers
// ---------------------------------------------------------------------------
__global__ __launch_bounds__(128, 2) void qkv_mma(
    const float* __restrict__ bq, const float* __restrict__ bk,
    const float* __restrict__ bv)
{
    const int z = blockIdx.z;
    const float* bias = (z == 0) ? bq : (z == 1) ? bk : bv;
    __half* out = (z == 0) ? g_q : (z == 1) ? g_k : g_v;
    const __half* B = g_wt + (size_t)z * CC * HH;
    gemm_tile<0, false>(g_x, CC, B, CC, out, HH,
                        blockIdx.y * TM, blockIdx.x * TN, CC, bias, 1.0f, 0);
}

// Compact lower-triangular grid: 136 live tiles per batch, 544 CTAs total.
__global__ __launch_bounds__(128, 2) void scores_mma()
{
    const int b = blockIdx.x / 136;
    const int tidx = blockIdx.x % 136;
    int mi = (int)((sqrtf(8.0f * (float)tidx + 1.0f) - 1.0f) * 0.5f);
    while ((mi + 1) * (mi + 2) / 2 <= tidx) mi++;
    while (mi * (mi + 1) / 2 > tidx) mi--;
    const int nj = tidx - mi * (mi + 1) / 2;

    const __half* q = g_q + (size_t)b * TT * HH;
    const __half* k = g_k + (size_t)b * TT * HH;
    float* psum = g_psum + (size_t)(b * TT + mi * TM) * 32;
    __half* P = g_p + (size_t)b * TT * TT;
    if (nj == mi)
        gemm_tile<1, true>(q, HH, k, HH, P, TT,
                           mi * TM, nj * TN, HH, psum, QK_SCALE_LOG2E, nj * 2);
    else
        gemm_tile<1, false>(q, HH, k, HH, P, TT,
                            mi * TM, nj * TN, HH, psum, QK_SCALE_LOG2E, nj * 2);
}

// Globally length-sorted 1D grid: level = idx/24 -> mi = 15-level (all 4
// batches' equal-K tiles adjacent), so wave 2 holds only the shortest tiles.
__global__ __launch_bounds__(128, 2) void pv_mma(float* __restrict__ out)
{
    const int idx = blockIdx.x;            // 0..383
    const int mi  = 15 - idx / 24;
    const int r   = idx % 24;
    const int nj  = r % 6;
    const int b   = r / 6;
    const __half* P = g_p + (size_t)b * TT * TT;
    const __half* V = g_v + (size_t)b * TT * HH;          // [t][h]
    gemm_tile<2, false>(P, TT, V, HH, out + (size_t)b * TT * HH, HH,
                        mi * TM, nj * TN, (mi + 1) * TM,
                        g_psum + (size_t)b * TT * 32, 1.0f, 0);
}

// ---------------------------------------------------------------------------
// Convert x to fp16 (8 elements/thread); first 256 blocks also zero g_psum.
// ---------------------------------------------------------------------------
__global__ __launch_bounds__(256) void conv_x_kernel(const float* __restrict__ x)
{
    size_t i = (size_t)blockIdx.x * 256 + threadIdx.x;
    if (blockIdx.x < 256) {
        ((float4*)g_psum)[i] = make_float4(0.f, 0.f, 0.f, 0.f);
    }
    const float4* p = (const float4*)x + 2 * i;
    float4 v0 = p[0], v1 = p[1];
    __half2 h[4];
    h[0] = __floats2half2_rn(v0.x, v0.y);
    h[1] = __floats2half2_rn(v0.z, v0.w);
    h[2] = __floats2half2_rn(v1.x, v1.y);
    h[3] = __floats2half2_rn(v1.z, v1.w);
    ((uint4*)g_x)[i] = *(uint4*)h;
}

// ---------------------------------------------------------------------------
// W transpose (to fp16)
// ---------------------------------------------------------------------------
__global__ void transpose_w_kernel(const float* __restrict__ Wq,
                                   const float* __restrict__ Wk,
                                   const float* __restrict__ Wv)
{
    const int z = blockIdx.z;
    const float* src = (z == 0) ? Wq : (z == 1) ? Wk : Wv;
    __half* dst = g_wt + (size_t)z * CC * HH;
    __shared__ float t[32][33];
    const int c0 = blockIdx.x * 32, r0 = blockIdx.y * 32;
    const int tx = threadIdx.x, ty = threadIdx.y;
    #pragma unroll
    for (int i = 0; i < 4; i++)
        t[ty + 8 * i][tx] = src[(size_t)(r0 + ty + 8 * i) * HH + c0 + tx];
    __syncthreads();
    #pragma unroll
    for (int i = 0; i < 4; i++)
        dst[(size_t)(c0 + ty + 8 * i) * CC + r0 + tx] =
            __float2half_rn(t[tx][ty + 8 * i]);
}

// ---------------------------------------------------------------------------
// Launch (scores_mma is the 4th launch — ncu's profiled slot)
// ---------------------------------------------------------------------------
extern "C" void kernel_launch(void* const* d_in, const int* in_sizes, int n_in,
                              void* d_out, int out_size)
{
    const float* x  = (const float*)d_in[0];
    const float* Wq = (const float*)d_in[1];
    const float* bq = (const float*)d_in[2];
    const float* Wk = (const float*)d_in[3];
    const float* bk = (const float*)d_in[4];
    const float* Wv = (const float*)d_in[5];
    const float* bv = (const float*)d_in[6];
    float* out = (float*)d_out;

    cudaFuncSetAttribute(qkv_mma, cudaFuncAttributeMaxDynamicSharedMemorySize, SMEM_BYTES);
    cudaFuncSetAttribute(scores_mma, cudaFuncAttributeMaxDynamicSharedMemorySize, SMEM_BYTES);
    cudaFuncSetAttribute(pv_mma, cudaFuncAttributeMaxDynamicSharedMemorySize, SMEM_BYTES);

    conv_x_kernel<<<MTOT * CC / (256 * 8), 256>>>(x);
    transpose_w_kernel<<<dim3(HH / 32, CC / 32, 3), dim3(32, 8)>>>(Wq, Wk, Wv);
    qkv_mma<<<dim3(HH / TN, MTOT / TM, 3), 128, SMEM_BYTES>>>(bq, bk, bv);
    scores_mma<<<dim3(136 * BB), 128, SMEM_BYTES>>>();
    pv_mma<<<dim3(384), 128, SMEM_BYTES>>>(out);
}

// round 16
// speedup vs baseline: 1.1837x; 1.0421x over previous
#include <cuda_runtime.h>
#include <cuda_fp16.h>
#include <math_constants.h>
#include <cstdint>

// ---------------------------------------------------------------------------
// Problem constants
// ---------------------------------------------------------------------------
#define BB 4
#define TT 2048
#define CC 768
#define HH 768
#define MTOT (BB * TT)           // 8192
static const float QK_SCALE_LOG2E = 0.05205971894527108f; // (1/sqrt(768))*log2(e)

// ---------------------------------------------------------------------------
// Scratch globals
// ---------------------------------------------------------------------------
__device__ __half g_x   [(size_t)MTOT * CC];
__device__ __half g_wt  [(size_t)3 * CC * HH];   // W^T  [z][n][k]
__device__ __half g_q   [(size_t)MTOT * HH];
__device__ __half g_k   [(size_t)MTOT * HH];
__device__ __half g_v   [(size_t)MTOT * HH];     // [t][h] per batch
__device__ __half g_p   [(size_t)BB * TT * TT];  // exp(scores) fp16 (unnormalized)
__device__ float  g_psum[(size_t)MTOT * 32];     // per-(row, tile-half) partial sums

// ---------------------------------------------------------------------------
// GEMM config: CTA 128x128, 128 threads (4 warps 2x2), warp tile 64x64,
// fp16 m16n8k16 mma, K-chunk 64, 3-stage cp.async, ldmatrix.x4 fragments.
// Epilogues stage results in (now-dead) pipeline smem with bank-padded
// strides, then write out with dense 16B stores (scattered STG.32 was the
// shared epilogue tax across all three GEMMs).
// MODE 0: qkv    (half out + bias)
// MODE 1: scores (softmax epilogue; MASK only on diagonal tiles)
// MODE 2: pv     (float out; rowsum reduced from psum in epilogue)
// ---------------------------------------------------------------------------
#define TM 128
#define TN 128
#define TK 64
#define STAGE_BYTES (2 * 128 * 128)       // A(16KB) + B(16KB)
#define NSTAGE 3
#define SMEM_BYTES (NSTAGE * STAGE_BYTES) // 98304 -> 2 CTAs/SM

__device__ __forceinline__ uint32_t smem_u32(const void* p) {
    uint32_t a;
    asm("{ .reg .u64 t; cvta.to.shared.u64 t, %1; cvt.u32.u64 %0, t; }"
        : "=r"(a) : "l"(p));
    return a;
}

__device__ __forceinline__ void cp16(uint32_t dst, const void* src) {
    asm volatile("cp.async.cg.shared.global [%0], [%1], 16;"
                 :: "r"(dst), "l"(src) : "memory");
}

__device__ __forceinline__ void ldsm_x4(uint32_t r[4], uint32_t addr) {
    asm volatile("ldmatrix.sync.aligned.m8n8.x4.shared.b16 {%0,%1,%2,%3}, [%4];"
                 : "=r"(r[0]), "=r"(r[1]), "=r"(r[2]), "=r"(r[3]) : "r"(addr));
}

__device__ __forceinline__ void ldsm_x4_t(uint32_t r[4], uint32_t addr) {
    asm volatile("ldmatrix.sync.aligned.m8n8.x4.trans.shared.b16 {%0,%1,%2,%3}, [%4];"
                 : "=r"(r[0]), "=r"(r[1]), "=r"(r[2]), "=r"(r[3]) : "r"(addr));
}

__device__ __forceinline__ void mma_f16(float c[4], const uint32_t a[4],
                                        const uint32_t b0, const uint32_t b1) {
    asm volatile(
        "mma.sync.aligned.m16n8k16.row.col.f32.f16.f16.f32 "
        "{%0,%1,%2,%3}, {%4,%5,%6,%7}, {%8,%9}, {%0,%1,%2,%3};"
        : "+f"(c[0]), "+f"(c[1]), "+f"(c[2]), "+f"(c[3])
        : "r"(a[0]), "r"(a[1]), "r"(a[2]), "r"(a[3]), "r"(b0), "r"(b1));
}

// ---------------------------------------------------------------------------
// Generic 128x128 fp16 mma.sync GEMM tile.
// aux: MODE 0 = bias; MODE 1 = psum row base (g_psum + (b*TT+row0)*32);
//      MODE 2 = psum batch-local base (g_psum + b*TT*32).
// ---------------------------------------------------------------------------
template <int MODE, bool MASK>
__device__ __forceinline__ void gemm_tile(
    const __half* __restrict__ A, int lda,
    const __half* __restrict__ B, int ldb,
    void* __restrict__ Cv, int ldc,
    int row0, int col0, int K,
    const void* __restrict__ aux, float scale, int pcol)
{
    constexpr bool TRANSB = (MODE == 2);
    extern __shared__ float smf[];
    const uint32_t sbase = smem_u32(smf);

    const int tid   = threadIdx.x;
    const int warp  = tid >> 5;
    const int lane  = tid & 31;
    const int wm    = (warp & 1) * 64;
    const int wn    = (warp >> 1) * 64;
    const int g     = lane >> 2;
    const int t     = lane & 3;

    const __half* Arow = A + (size_t)row0 * lda;
    const __half* Brow = TRANSB ? (B + col0) : (B + (size_t)col0 * ldb);
    const int NC = K / TK;

    float acc[4][8][4];
    #pragma unroll
    for (int mi = 0; mi < 4; mi++)
        #pragma unroll
        for (int ni = 0; ni < 8; ni++)
            #pragma unroll
            for (int j = 0; j < 4; j++) acc[mi][ni][j] = 0.0f;

    uint32_t stA[NSTAGE], stB[NSTAGE];
    #pragma unroll
    for (int s = 0; s < NSTAGE; s++) {
        stA[s] = sbase + (uint32_t)(s * STAGE_BYTES);
        stB[s] = stA[s] + (uint32_t)(128 * 128);
    }

    auto load_chunk = [&](uint32_t sA, uint32_t sB, int c) {
        const __half* Ag = Arow + c * TK;
        #pragma unroll
        for (int i = 0; i < 8; i++) {            // A: 128 rows x 8 granules
            int idx = tid + i * 128;
            int row = idx >> 3, gc = idx & 7;
            uint32_t off = (uint32_t)(row * 128 + ((gc * 16) ^ ((row & 7) * 16)));
            cp16(sA + off, Ag + (size_t)row * lda + gc * 8);
        }
        if (TRANSB) {
            const __half* Bg = Brow + (size_t)c * TK * ldb;
            #pragma unroll
            for (int i = 0; i < 8; i++) {        // B: 64 k-rows x 16 granules
                int idx = tid + i * 128;
                int row = idx >> 4, gc = idx & 15;
                uint32_t off = (uint32_t)(row * 256 + ((gc * 16) ^ ((row & 7) * 16)));
                cp16(sB + off, Bg + (size_t)row * ldb + gc * 8);
            }
        } else {
            const __half* Bg = Brow + c * TK;
            #pragma unroll
            for (int i = 0; i < 8; i++) {        // B: 128 n-rows x 8 granules
                int idx = tid + i * 128;
                int row = idx >> 3, gc = idx & 7;
                uint32_t off = (uint32_t)(row * 128 + ((gc * 16) ^ ((row & 7) * 16)));
                cp16(sB + off, Bg + (size_t)row * ldb + gc * 8);
            }
        }
    };

    #pragma unroll
    for (int s = 0; s < NSTAGE - 1; s++) {
        if (s < NC) load_chunk(stA[s], stB[s], s);
        asm volatile("cp.async.commit_group;" ::: "memory");
    }

    const uint32_t aRow = (uint32_t)(wm + (lane & 15)) * 128;
    const uint32_t bRow = (uint32_t)(wn + (lane & 15)) * 128;
    const uint32_t cHi  = (uint32_t)(lane >> 4) * 16;
    const uint32_t xr   = (uint32_t)(lane & 7) * 16;
    const uint32_t vRowB = (uint32_t)(lane & 15) * 256;
    uint32_t hx[4];
    #pragma unroll
    for (int p = 0; p < 4; p++)
        hx[p] = (uint32_t)((((wn >> 3) + 2 * p + (lane >> 4)) * 16) ^ ((lane & 7) * 16));

    #pragma unroll 1
    for (int c = 0; c < NC; c++) {
        asm volatile("cp.async.wait_group %0;" :: "n"(NSTAGE - 2) : "memory");
        __syncthreads();

        const int cn = c + NSTAGE - 1;
        if (cn < NC)
            load_chunk(stA[cn % NSTAGE], stB[cn % NSTAGE], cn);
        asm volatile("cp.async.commit_group;" ::: "memory");

        const int s = c % NSTAGE;
        const uint32_t aB = stA[s] + aRow;

        #pragma unroll
        for (int ks = 0; ks < 4; ks++) {
            uint32_t a[4][4], bf[4][4];
            const uint32_t koff = ((uint32_t)(2 * ks) * 16 + cHi) ^ xr;
            #pragma unroll
            for (int mi = 0; mi < 4; mi++)
                ldsm_x4(a[mi], aB + (uint32_t)mi * 2048 + koff);

            if (TRANSB) {
                const uint32_t bB = stB[s] + (uint32_t)ks * 4096 + vRowB;
                #pragma unroll
                for (int p = 0; p < 4; p++)
                    ldsm_x4_t(bf[p], bB + hx[p]);
                #pragma unroll
                for (int mi = 0; mi < 4; mi++)
                    #pragma unroll
                    for (int p = 0; p < 4; p++) {
                        mma_f16(acc[mi][2 * p],     a[mi], bf[p][0], bf[p][1]);
                        mma_f16(acc[mi][2 * p + 1], a[mi], bf[p][2], bf[p][3]);
                    }
            } else {
                const uint32_t bB = stB[s] + bRow;
                #pragma unroll
                for (int p = 0; p < 4; p++)
                    ldsm_x4(bf[p], bB + (uint32_t)p * 2048 + koff);
                #pragma unroll
                for (int mi = 0; mi < 4; mi++)
                    #pragma unroll
                    for (int p = 0; p < 4; p++) {
                        mma_f16(acc[mi][2 * p],     a[mi], bf[p][0], bf[p][2]);
                        mma_f16(acc[mi][2 * p + 1], a[mi], bf[p][1], bf[p][3]);
                    }
            }
        }
    }

    // ------------------------------------------------------------- Epilogue
    // Pipeline smem is dead past this barrier; reuse it as a bank-padded
    // staging tile so global stores go out as dense 16B transactions.
    __syncthreads();

    if (MODE == 0 || MODE == 1) {
        // half staging: row stride 68 words (136 halfs); STS.32 banks = 4g+t,
        // conflict-free.
        uint32_t* st = (uint32_t*)smf;
        const int colw = (wn >> 1) + t;
        float* psum = (MODE == 1) ? (float*)aux : nullptr;
        const int pc = (MODE == 1) ? (pcol + (wn >> 6)) : 0;

        #pragma unroll
        for (int mi = 0; mi < 4; mi++) {
            const int lA = wm + mi * 16 + g;      // CTA-local rows
            const int lB = lA + 8;
            const int rA = row0 + lA;             // global rows (for mask)
            const int rB = row0 + lB;
            float sumA = 0.0f, sumB = 0.0f;
            #pragma unroll
            for (int ni = 0; ni < 8; ni++) {
                float v0, v1, v2, v3;
                if (MODE == 1) {
                    v0 = exp2f(acc[mi][ni][0] * scale);
                    v1 = exp2f(acc[mi][ni][1] * scale);
                    v2 = exp2f(acc[mi][ni][2] * scale);
                    v3 = exp2f(acc[mi][ni][3] * scale);
                    if (MASK) {
                        const int ccol = col0 + wn + ni * 8 + 2 * t;
                        if (ccol     > rA) v0 = 0.0f;
                        if (ccol + 1 > rA) v1 = 0.0f;
                        if (ccol     > rB) v2 = 0.0f;
                        if (ccol + 1 > rB) v3 = 0.0f;
                    }
                    sumA += v0 + v1;
                    sumB += v2 + v3;
                } else {
                    const float* bias = (const float*)aux;
                    const int ccol = col0 + wn + ni * 8 + 2 * t;
                    float b0 = bias[ccol], b1 = bias[ccol + 1];
                    v0 = acc[mi][ni][0] + b0; v1 = acc[mi][ni][1] + b1;
                    v2 = acc[mi][ni][2] + b0; v3 = acc[mi][ni][3] + b1;
                }
                __half2 h01 = __floats2half2_rn(v0, v1);
                __half2 h23 = __floats2half2_rn(v2, v3);
                st[lA * 68 + colw + ni * 4] = *(uint32_t*)&h01;
                st[lB * 68 + colw + ni * 4] = *(uint32_t*)&h23;
            }
            if (MODE == 1) {
                sumA += __shfl_xor_sync(0xffffffffu, sumA, 1);
                sumA += __shfl_xor_sync(0xffffffffu, sumA, 2);
                sumB += __shfl_xor_sync(0xffffffffu, sumB, 1);
                sumB += __shfl_xor_sync(0xffffffffu, sumB, 2);
                if (t == 0) {
                    psum[(size_t)lA * 32 + pc] = sumA;
                    psum[(size_t)lB * 32 + pc] = sumB;
                }
            }
        }
        __syncthreads();
        // Coalesced copy-out: 128 rows x 16 granules (16B each).
        __half* C = (__half*)Cv;
        #pragma unroll
        for (int it = 0; it < 16; it++) {
            const int gi = tid + it * 128;
            const int row = gi >> 4, gc = gi & 15;
            uint4 v = *(const uint4*)(smf + row * 68 + gc * 4);
            *(uint4*)(C + (size_t)(row0 + row) * ldc + col0 + gc * 8) = v;
        }
        return;
    }

    // MODE 2: float staging, row stride 132 words (528B).
    {
        #pragma unroll
        for (int mi = 0; mi < 4; mi++) {
            const int lA = wm + mi * 16 + g;
            const int lB = lA + 8;
            const int r0 = row0 + lA;
            // Rowsum from psum (batch-local base in aux).
            const float* psum = (const float*)aux;
            const float4* p0 = (const float4*)(psum + (size_t)r0 * 32) + t * 2;
            const float4* p8 = (const float4*)(psum + (size_t)(r0 + 8) * 32) + t * 2;
            float4 a0 = p0[0], a1 = p0[1];
            float4 b0 = p8[0], b1 = p8[1];
            float s0 = (a0.x + a0.y) + (a0.z + a0.w) + (a1.x + a1.y) + (a1.z + a1.w);
            float s8 = (b0.x + b0.y) + (b0.z + b0.w) + (b1.x + b1.y) + (b1.z + b1.w);
            s0 += __shfl_xor_sync(0xffffffffu, s0, 1);
            s0 += __shfl_xor_sync(0xffffffffu, s0, 2);
            s8 += __shfl_xor_sync(0xffffffffu, s8, 1);
            s8 += __shfl_xor_sync(0xffffffffu, s8, 2);
            const float rs0 = 1.0f / s0;
            const float rs8 = 1.0f / s8;
            #pragma unroll
            for (int ni = 0; ni < 8; ni++) {
                const int cw = wn + ni * 8 + 2 * t;
                *(float2*)(smf + lA * 132 + cw) =
                    make_float2(acc[mi][ni][0] * rs0, acc[mi][ni][1] * rs0);
                *(float2*)(smf + lB * 132 + cw) =
                    make_float2(acc[mi][ni][2] * rs8, acc[mi][ni][3] * rs8);
            }
        }
        __syncthreads();
        // Coalesced copy-out: 128 rows x 32 granules (16B each).
        float* C = (float*)Cv;
        #pragma unroll
        for (int it = 0; it < 32; it++) {
            const int gi = tid + it * 128;
            const int row = gi >> 5, gc = gi & 31;
            uint4 v = *(const uint4*)(smf + row * 132 + gc * 4);
            *(uint4*)(C + (size_t)(row0 + row) * ldc + col0 + gc * 4) = v;
        }
    }
}

// ---------------------------------------------------------------------------
// GEMM wrappers
// ---------------------------------------------------------------------------
__global__ __launch_bounds__(128, 2) void qkv_mma(
    const float* __restrict__ bq, const float* __restrict__ bk,
    const float* __restrict__ bv)
{
    const int z = blockIdx.z;
    const float* bias = (z == 0) ? bq : (z == 1) ? bk : bv;
    __half* out = (z == 0) ? g_q : (z == 1) ? g_k : g_v;
    const __half* B = g_wt + (size_t)z * CC * HH;
    gemm_tile<0, false>(g_x, CC, B, CC, out, HH,
                        blockIdx.y * TM, blockIdx.x * TN, CC, bias, 1.0f, 0);
}

// Compact lower-triangular grid: 136 live tiles per batch, 544 CTAs total.
__global__ __launch_bounds__(128, 2) void scores_mma()
{
    const int b = blockIdx.x / 136;
    const int tidx = blockIdx.x % 136;
    int mi = (int)((sqrtf(8.0f * (float)tidx + 1.0f) - 1.0f) * 0.5f);
    while ((mi + 1) * (mi + 2) / 2 <= tidx) mi++;
    while (mi * (mi + 1) / 2 > tidx) mi--;
    const int nj = tidx - mi * (mi + 1) / 2;

    const __half* q = g_q + (size_t)b * TT * HH;
    const __half* k = g_k + (size_t)b * TT * HH;
    float* psum = g_psum + (size_t)(b * TT + mi * TM) * 32;
    __half* P = g_p + (size_t)b * TT * TT;
    if (nj == mi)
        gemm_tile<1, true>(q, HH, k, HH, P, TT,
                           mi * TM, nj * TN, HH, psum, QK_SCALE_LOG2E, nj * 2);
    else
        gemm_tile<1, false>(q, HH, k, HH, P, TT,
                            mi * TM, nj * TN, HH, psum, QK_SCALE_LOG2E, nj * 2);
}

// Globally length-sorted 1D grid: level = idx/24 -> mi = 15-level.
__global__ __launch_bounds__(128, 2) void pv_mma(float* __restrict__ out)
{
    const int idx = blockIdx.x;            // 0..383
    const int mi  = 15 - idx / 24;
    const int r   = idx % 24;
    const int nj  = r % 6;
    const int b   = r / 6;
    const __half* P = g_p + (size_t)b * TT * TT;
    const __half* V = g_v + (size_t)b * TT * HH;          // [t][h]
    gemm_tile<2, false>(P, TT, V, HH, out + (size_t)b * TT * HH, HH,
                        mi * TM, nj * TN, (mi + 1) * TM,
                        g_psum + (size_t)b * TT * 32, 1.0f, 0);
}

// ---------------------------------------------------------------------------
// Prep: W transpose (blocks 0..1727) + x->fp16 convert (blocks 1728..4799);
// first 256 convert blocks also zero g_psum.
// ---------------------------------------------------------------------------
__global__ __launch_bounds__(256) void prep_kernel(
    const float* __restrict__ x,
    const float* __restrict__ Wq, const float* __restrict__ Wk,
    const float* __restrict__ Wv)
{
    const int bx = blockIdx.x;
    if (bx < 1728) {                       // 3 * 24 * 24 transpose blocks
        const int z = bx / 576;
        const int rr = bx % 576;
        const int byy = rr / 24, bxx = rr % 24;
        const float* src = (z == 0) ? Wq : (z == 1) ? Wk : Wv;
        __half* dst = g_wt + (size_t)z * CC * HH;
        __shared__ float tbuf[32][33];
        const int tx = threadIdx.x & 31, ty = threadIdx.x >> 5;
        const int c0 = bxx * 32, r0 = byy * 32;
        #pragma unroll
        for (int i = 0; i < 4; i++)
            tbuf[ty + 8 * i][tx] = src[(size_t)(r0 + ty + 8 * i) * HH + c0 + tx];
        __syncthreads();
        #pragma unroll
        for (int i = 0; i < 4; i++)
            dst[(size_t)(c0 + ty + 8 * i) * CC + r0 + tx] =
                __float2half_rn(tbuf[tx][ty + 8 * i]);
    } else {
        const int cb = bx - 1728;          // 3072 convert blocks
        size_t i = (size_t)cb * 256 + threadIdx.x;
        if (cb < 256)
            ((float4*)g_psum)[i] = make_float4(0.f, 0.f, 0.f, 0.f);
        const float4* p = (const float4*)x + 2 * i;
        float4 v0 = p[0], v1 = p[1];
        __half2 h[4];
        h[0] = __floats2half2_rn(v0.x, v0.y);
        h[1] = __floats2half2_rn(v0.z, v0.w);
        h[2] = __floats2half2_rn(v1.x, v1.y);
        h[3] = __floats2half2_rn(v1.z, v1.w);
        ((uint4*)g_x)[i] = *(uint4*)h;
    }
}

// ---------------------------------------------------------------------------
// Launch: prep(1), qkv(2), scores(3), pv(4 — ncu's profiled slot)
// ---------------------------------------------------------------------------
extern "C" void kernel_launch(void* const* d_in, const int* in_sizes, int n_in,
                              void* d_out, int out_size)
{
    const float* x  = (const float*)d_in[0];
    const float* Wq = (const float*)d_in[1];
    const float* bq = (const float*)d_in[2];
    const float* Wk = (const float*)d_in[3];
    const float* bk = (const float*)d_in[4];
    const float* Wv = (const float*)d_in[5];
    const float* bv = (const float*)d_in[6];
    float* out = (float*)d_out;

    cudaFuncSetAttribute(qkv_mma, cudaFuncAttributeMaxDynamicSharedMemorySize, SMEM_BYTES);
    cudaFuncSetAttribute(scores_mma, cudaFuncAttributeMaxDynamicSharedMemorySize, SMEM_BYTES);
    cudaFuncSetAttribute(pv_mma, cudaFuncAttributeMaxDynamicSharedMemorySize, SMEM_BYTES);

    prep_kernel<<<dim3(1728 + 3072), 256>>>(x, Wq, Wk, Wv);
    qkv_mma<<<dim3(HH / TN, MTOT / TM, 3), 128, SMEM_BYTES>>>(bq, bk, bv);
    scores_mma<<<dim3(136 * BB), 128, SMEM_BYTES>>>();
    pv_mma<<<dim3(384), 128, SMEM_BYTES>>>(out);
}